// round 2
// baseline (speedup 1.0000x reference)
#include <cuda_runtime.h>
#include <cuda_bf16.h>
#include <math.h>

// Problem constants
#define BATCH 16
#define NSEQ 4096
#define CDIM 512
#define PW 64
#define PH 64
#define PWH 32            // PW/POOL
#define MTOT (BATCH * NSEQ)   // 65536 rows of x
#define ELEMS ((size_t)BATCH * CDIM * NSEQ)  // 33554432

// Scratch (channel-major [B][C][N]) — __device__ globals (no allocation allowed)
__device__ float g_Q[ELEMS];
__device__ float g_K[ELEMS];
__device__ float g_V[ELEMS];
__device__ float g_O[ELEMS];

// ---------------------------------------------------------------------------
// Projection GEMM: out[(b*512+d)*4096 + n] = sigmoid( sum_c x[bn, c] * W[d, c] + bias[d] )
// M dim = d (cout, 512), N dim = bn (65536), K = 512. 128x128x16 tile, 8x8/thread.
// ---------------------------------------------------------------------------
__global__ __launch_bounds__(256) void proj_kernel(
    const float* __restrict__ x,    // [65536, 512]
    const float* __restrict__ W,    // [512, 512]
    const float* __restrict__ bias, // [512]
    float* __restrict__ out)        // [B*C, 4096]
{
    const int n0 = blockIdx.x * 128;   // over bn
    const int d0 = blockIdx.y * 128;   // over cout

    __shared__ float sW[16][128];      // [k][d]
    __shared__ float sX[16][128];      // [k][n]

    const int tid = threadIdx.x;
    const int tx  = tid & 15;          // n subtile
    const int ty  = tid >> 4;          // d subtile

    const int lr = tid >> 2;           // 0..63 : row within tile
    const int lk = (tid & 3) << 2;     // 0,4,8,12 : k offset

    float acc[8][8];
    #pragma unroll
    for (int i = 0; i < 8; ++i)
        #pragma unroll
        for (int j = 0; j < 8; ++j) acc[i][j] = 0.f;

    for (int k0 = 0; k0 < 512; k0 += 16) {
        #pragma unroll
        for (int h = 0; h < 2; ++h) {
            int r = lr + h * 64;
            float4 w4 = *(const float4*)(W + (size_t)(d0 + r) * 512 + k0 + lk);
            sW[lk + 0][r] = w4.x; sW[lk + 1][r] = w4.y;
            sW[lk + 2][r] = w4.z; sW[lk + 3][r] = w4.w;
            float4 x4 = *(const float4*)(x + (size_t)(n0 + r) * 512 + k0 + lk);
            sX[lk + 0][r] = x4.x; sX[lk + 1][r] = x4.y;
            sX[lk + 2][r] = x4.z; sX[lk + 3][r] = x4.w;
        }
        __syncthreads();
        #pragma unroll
        for (int kk = 0; kk < 16; ++kk) {
            float a[8], b[8];
            #pragma unroll
            for (int i = 0; i < 8; ++i) a[i] = sW[kk][ty * 8 + i];
            #pragma unroll
            for (int j = 0; j < 8; ++j) b[j] = sX[kk][tx * 8 + j];
            #pragma unroll
            for (int i = 0; i < 8; ++i)
                #pragma unroll
                for (int j = 0; j < 8; ++j)
                    acc[i][j] = fmaf(a[i], b[j], acc[i][j]);
        }
        __syncthreads();
    }

    const int b   = n0 >> 12;                 // n0 / 4096 (block never crosses batch)
    const int nn0 = (n0 & 4095) + tx * 8;
    #pragma unroll
    for (int i = 0; i < 8; ++i) {
        int d = d0 + ty * 8 + i;
        float bb = bias[d];
        float* orow = out + (((size_t)(b * 512 + d)) << 12) + nn0;
        #pragma unroll
        for (int j = 0; j < 8; j += 4) {
            float4 v;
            v.x = 1.f / (1.f + __expf(-(acc[i][j + 0] + bb)));
            v.y = 1.f / (1.f + __expf(-(acc[i][j + 1] + bb)));
            v.z = 1.f / (1.f + __expf(-(acc[i][j + 2] + bb)));
            v.w = 1.f / (1.f + __expf(-(acc[i][j + 3] + bb)));
            *(float4*)(orow + j) = v;
        }
    }
}

// ---------------------------------------------------------------------------
// Attention: one block per (b,c). Loads 64x64 Q/K/V, pools, two softmax-matmul
// chains, writes [B][C][N] output. Padded smem rows (stride 65 / 33).
// ---------------------------------------------------------------------------
#define S64 65
#define S32 33
#define ATT_SMEM_FLOATS (3 * 64 * S64 + 4 * 32 * S64 + 64 * S32)
#define ATT_SMEM_BYTES (ATT_SMEM_FLOATS * 4)

__global__ __launch_bounds__(256) void attn_kernel(
    const float* __restrict__ gQ,
    const float* __restrict__ gK,
    const float* __restrict__ gV,
    float* __restrict__ gO)
{
    extern __shared__ float sm[];
    float* sQ   = sm;                    // 64 x S64
    float* sK   = sQ   + 64 * S64;       // 64 x S64
    float* sV   = sK   + 64 * S64;       // 64 x S64
    float* sq   = sV   + 64 * S64;       // 32 x S64 (pooled Q)
    float* sk   = sq   + 32 * S64;       // 32 x S64 (pooled K)
    float* sKq  = sk   + 32 * S64;       // 32 x S64
    float* sKqv = sKq  + 32 * S64;       // 32 x S64
    float* sQk  = sKqv + 32 * S64;       // 64 x S32

    const int bc = blockIdx.x;           // b*512 + c
    const size_t base = (size_t)bc * 4096;
    const int tid = threadIdx.x;

    // load Q, K, V tiles (contiguous 4096 floats each)
    for (int idx = tid; idx < 1024; idx += 256) {
        int row = idx >> 4;
        int c4  = (idx & 15) << 2;
        float4 q4 = *(const float4*)(gQ + base + (row << 6) + c4);
        float4 k4 = *(const float4*)(gK + base + (row << 6) + c4);
        float4 v4 = *(const float4*)(gV + base + (row << 6) + c4);
        float* dq = sQ + row * S64 + c4;
        float* dk = sK + row * S64 + c4;
        float* dv = sV + row * S64 + c4;
        dq[0] = q4.x; dq[1] = q4.y; dq[2] = q4.z; dq[3] = q4.w;
        dk[0] = k4.x; dk[1] = k4.y; dk[2] = k4.z; dk[3] = k4.w;
        dv[0] = v4.x; dv[1] = v4.y; dv[2] = v4.z; dv[3] = v4.w;
    }
    __syncthreads();

    // pool over PW axis (pairs of rows)
    for (int idx = tid; idx < 2048; idx += 256) {
        int i  = idx >> 6;
        int ph = idx & 63;
        sq[i * S64 + ph] = 0.5f * (sQ[(2 * i) * S64 + ph] + sQ[(2 * i + 1) * S64 + ph]);
        sk[i * S64 + ph] = 0.5f * (sK[(2 * i) * S64 + ph] + sK[(2 * i + 1) * S64 + ph]);
    }
    __syncthreads();

    const float scale = 0.044194173824159216f; // 1/sqrt(512)

    // S1: sQk[i][j] = scale * sum_ph sQ[i][ph] * sk[j][ph]   (64 x 32)
    {
        const int tr = tid >> 3;   // rows 2tr, 2tr+1
        const int tc = tid & 7;    // cols 4tc..4tc+3
        float acc[2][4] = {{0.f,0.f,0.f,0.f},{0.f,0.f,0.f,0.f}};
        const float* qr0 = sQ + (2 * tr) * S64;
        const float* qr1 = qr0 + S64;
        #pragma unroll 8
        for (int ph = 0; ph < 64; ++ph) {
            float a0 = qr0[ph], a1 = qr1[ph];
            #pragma unroll
            for (int j = 0; j < 4; ++j) {
                float bb = sk[(4 * tc + j) * S64 + ph];
                acc[0][j] = fmaf(a0, bb, acc[0][j]);
                acc[1][j] = fmaf(a1, bb, acc[1][j]);
            }
        }
        #pragma unroll
        for (int ii = 0; ii < 2; ++ii)
            #pragma unroll
            for (int j = 0; j < 4; ++j)
                sQk[(2 * tr + ii) * S32 + 4 * tc + j] = acc[ii][j] * scale;
    }
    __syncthreads();

    // softmax over rows of sQk (64 rows x 32)
    if (tid < 64) {
        float* row = sQk + tid * S32;
        float m = row[0];
        #pragma unroll 8
        for (int j = 1; j < 32; ++j) m = fmaxf(m, row[j]);
        float s = 0.f;
        #pragma unroll 8
        for (int j = 0; j < 32; ++j) { float e = __expf(row[j] - m); row[j] = e; s += e; }
        float inv = 1.f / s;
        #pragma unroll 8
        for (int j = 0; j < 32; ++j) row[j] *= inv;
    }

    // S2: sKq[i][j] = scale * sum_ph sq[i][ph] * sK[j][ph]   (32 x 64)
    {
        const int tr = tid >> 4;   // rows 2tr, 2tr+1 (0..31)
        const int tc = tid & 15;   // cols 4tc..4tc+3 (0..63)
        float acc[2][4] = {{0.f,0.f,0.f,0.f},{0.f,0.f,0.f,0.f}};
        const float* qr0 = sq + (2 * tr) * S64;
        const float* qr1 = qr0 + S64;
        #pragma unroll 8
        for (int ph = 0; ph < 64; ++ph) {
            float a0 = qr0[ph], a1 = qr1[ph];
            #pragma unroll
            for (int j = 0; j < 4; ++j) {
                float bb = sK[(4 * tc + j) * S64 + ph];
                acc[0][j] = fmaf(a0, bb, acc[0][j]);
                acc[1][j] = fmaf(a1, bb, acc[1][j]);
            }
        }
        #pragma unroll
        for (int ii = 0; ii < 2; ++ii)
            #pragma unroll
            for (int j = 0; j < 4; ++j)
                sKq[(2 * tr + ii) * S64 + 4 * tc + j] = acc[ii][j] * scale;
    }
    __syncthreads();

    // softmax over rows of sKq (32 rows x 64)
    if (tid < 32) {
        float* row = sKq + tid * S64;
        float m = row[0];
        #pragma unroll 8
        for (int j = 1; j < 64; ++j) m = fmaxf(m, row[j]);
        float s = 0.f;
        #pragma unroll 8
        for (int j = 0; j < 64; ++j) { float e = __expf(row[j] - m); row[j] = e; s += e; }
        float inv = 1.f / s;
        #pragma unroll 8
        for (int j = 0; j < 64; ++j) row[j] *= inv;
    }
    __syncthreads();

    // S3: sKqv[i][ph] = sum_j sKq[i][j] * sV[j][ph]   (32 x 64, contract 64)
    {
        const int tr = tid >> 4;   // rows 2tr, 2tr+1
        const int tc = tid & 15;   // cols 4tc..4tc+3
        float acc[2][4] = {{0.f,0.f,0.f,0.f},{0.f,0.f,0.f,0.f}};
        const float* r0 = sKq + (2 * tr) * S64;
        const float* r1 = r0 + S64;
        #pragma unroll 8
        for (int j = 0; j < 64; ++j) {
            float a0 = r0[j], a1 = r1[j];
            #pragma unroll
            for (int jj = 0; jj < 4; ++jj) {
                float bb = sV[j * S64 + 4 * tc + jj];
                acc[0][jj] = fmaf(a0, bb, acc[0][jj]);
                acc[1][jj] = fmaf(a1, bb, acc[1][jj]);
            }
        }
        #pragma unroll
        for (int ii = 0; ii < 2; ++ii)
            #pragma unroll
            for (int jj = 0; jj < 4; ++jj)
                sKqv[(2 * tr + ii) * S64 + 4 * tc + jj] = acc[ii][jj];
    }
    __syncthreads();

    // S4: out[i][ph] = sum_j sQk[i][j] * sKqv[j][ph]   (64 x 64, contract 32)
    {
        const int tr = tid >> 4;   // rows 4tr..4tr+3
        const int tc = tid & 15;   // cols 4tc..4tc+3
        float acc[4][4];
        #pragma unroll
        for (int i = 0; i < 4; ++i)
            #pragma unroll
            for (int j = 0; j < 4; ++j) acc[i][j] = 0.f;
        #pragma unroll 8
        for (int j = 0; j < 32; ++j) {
            float a[4], b[4];
            #pragma unroll
            for (int ii = 0; ii < 4; ++ii) a[ii] = sQk[(4 * tr + ii) * S32 + j];
            #pragma unroll
            for (int jj = 0; jj < 4; ++jj) b[jj] = sKqv[j * S64 + 4 * tc + jj];
            #pragma unroll
            for (int ii = 0; ii < 4; ++ii)
                #pragma unroll
                for (int jj = 0; jj < 4; ++jj)
                    acc[ii][jj] = fmaf(a[ii], b[jj], acc[ii][jj]);
        }
        #pragma unroll
        for (int ii = 0; ii < 4; ++ii) {
            float4 v = make_float4(acc[ii][0], acc[ii][1], acc[ii][2], acc[ii][3]);
            *(float4*)(gO + base + (4 * tr + ii) * 64 + 4 * tc) = v;
        }
    }
}

// ---------------------------------------------------------------------------
// Transpose [B][C][N] -> [B][N][C] (coalesced both sides via 32x32 smem tile)
// ---------------------------------------------------------------------------
__global__ __launch_bounds__(256) void transpose_kernel(
    const float* __restrict__ gO, float* __restrict__ out)
{
    __shared__ float tile[32][33];
    const int b  = blockIdx.z;
    const int n0 = blockIdx.x * 32;
    const int c0 = blockIdx.y * 32;
    const float* src = gO + ((size_t)b * 512) * 4096;
    #pragma unroll
    for (int i = threadIdx.y; i < 32; i += 8)
        tile[i][threadIdx.x] = src[(size_t)(c0 + i) * 4096 + n0 + threadIdx.x];
    __syncthreads();
    float* dst = out + ((size_t)b * 4096) * 512;
    #pragma unroll
    for (int i = threadIdx.y; i < 32; i += 8)
        dst[(size_t)(n0 + i) * 512 + c0 + threadIdx.x] = tile[threadIdx.x][i];
}

// ---------------------------------------------------------------------------
extern "C" void kernel_launch(void* const* d_in, const int* in_sizes, int n_in,
                              void* d_out, int out_size)
{
    (void)in_sizes; (void)n_in; (void)out_size;
    const float* x  = (const float*)d_in[0];
    const float* Wq = (const float*)d_in[1];
    const float* bq = (const float*)d_in[2];
    const float* Wk = (const float*)d_in[3];
    const float* bk = (const float*)d_in[4];
    const float* Wv = (const float*)d_in[5];
    const float* bv = (const float*)d_in[6];
    float* out = (float*)d_out;

    float *pQ, *pK, *pV, *pO;
    cudaGetSymbolAddress((void**)&pQ, g_Q);
    cudaGetSymbolAddress((void**)&pK, g_K);
    cudaGetSymbolAddress((void**)&pV, g_V);
    cudaGetSymbolAddress((void**)&pO, g_O);

    cudaFuncSetAttribute(attn_kernel,
                         cudaFuncAttributeMaxDynamicSharedMemorySize,
                         ATT_SMEM_BYTES);

    dim3 gproj(MTOT / 128, CDIM / 128);   // (512, 4)
    proj_kernel<<<gproj, 256>>>(x, Wq, bq, pQ);
    proj_kernel<<<gproj, 256>>>(x, Wk, bk, pK);
    proj_kernel<<<gproj, 256>>>(x, Wv, bv, pV);

    attn_kernel<<<BATCH * CDIM, 256, ATT_SMEM_BYTES>>>(pQ, pK, pV, pO);

    transpose_kernel<<<dim3(NSEQ / 32, CDIM / 32, BATCH), dim3(32, 8)>>>(pO, out);
}

// round 4
// speedup vs baseline: 2.0731x; 2.0731x over previous
#include <cuda_runtime.h>
#include <cuda_bf16.h>
#include <math.h>
#include <stdint.h>

// ---------------------------------------------------------------------------
// Problem constants
// ---------------------------------------------------------------------------
#define BATCH 16
#define NSEQ 4096
#define CDIM 512
#define MTOT (BATCH * NSEQ)                       // 65536
#define ELEMS ((size_t)BATCH * CDIM * NSEQ)       // 33554432

// Scratch (channel-major [B][C][N]) — __device__ globals (no allocation allowed)
__device__ float g_Q[ELEMS];
__device__ float g_K[ELEMS];
__device__ float g_V[ELEMS];
__device__ float g_O[ELEMS];

// bf16 hi/lo split scratch
__device__ __nv_bfloat16 g_xh[(size_t)MTOT * CDIM];
__device__ __nv_bfloat16 g_xl[(size_t)MTOT * CDIM];
__device__ __nv_bfloat16 g_wh[3 * CDIM * CDIM];
__device__ __nv_bfloat16 g_wl[3 * CDIM * CDIM];

__device__ __forceinline__ uint32_t smem_u32(const void* p) {
    uint32_t a;
    asm("{ .reg .u64 t; cvta.to.shared.u64 t, %1; cvt.u32.u64 %0, t; }"
        : "=r"(a) : "l"(p));
    return a;
}

// ---------------------------------------------------------------------------
// hi/lo bf16 split kernel (vectorized by 4 floats)
// ---------------------------------------------------------------------------
__global__ __launch_bounds__(256) void split_kernel(
    const float4* __restrict__ in,
    __nv_bfloat162* __restrict__ hi,
    __nv_bfloat162* __restrict__ lo,
    int n4)
{
    int i = blockIdx.x * 256 + threadIdx.x;
    if (i >= n4) return;
    float4 v = in[i];
    __nv_bfloat16 h0 = __float2bfloat16(v.x);
    __nv_bfloat16 h1 = __float2bfloat16(v.y);
    __nv_bfloat16 h2 = __float2bfloat16(v.z);
    __nv_bfloat16 h3 = __float2bfloat16(v.w);
    __nv_bfloat16 l0 = __float2bfloat16(v.x - __bfloat162float(h0));
    __nv_bfloat16 l1 = __float2bfloat16(v.y - __bfloat162float(h1));
    __nv_bfloat16 l2 = __float2bfloat16(v.z - __bfloat162float(h2));
    __nv_bfloat16 l3 = __float2bfloat16(v.w - __bfloat162float(h3));
    hi[2 * i]     = __halves2bfloat162(h0, h1);
    hi[2 * i + 1] = __halves2bfloat162(h2, h3);
    lo[2 * i]     = __halves2bfloat162(l0, l1);
    lo[2 * i + 1] = __halves2bfloat162(l2, l3);
}

// ---------------------------------------------------------------------------
// Projection GEMM via mma.sync (bf16, fp32 accum), 3-term hi/lo split.
//   out[(b*512+d)*4096 + n] = sigmoid( sum_c W[d,c]*x[bn,c] + bias[d] )
// CTA tile: M=128 (d) x N=128 (n), K streamed in 32-chunks, 2-stage cp.async.
// Warps: 2(M) x 4(N); warp tile 64x32; m16n8k16 fragments.
// ---------------------------------------------------------------------------
#define TSTRIDE 40                         // bf16 elems per smem row (pad 32->40)
#define TILE_ELEMS (128 * TSTRIDE)         // 5120 bf16
#define TILE_BYTES (TILE_ELEMS * 2)        // 10240
#define STAGE_BYTES (4 * TILE_BYTES)       // Ah,Al,Bh,Bl = 40960
#define PROJ_SMEM (2 * STAGE_BYTES)        // 81920

#define LDSM_X4(r0, r1, r2, r3, addr) \
    asm volatile("ldmatrix.sync.aligned.m8n8.x4.shared.b16 {%0,%1,%2,%3}, [%4];" \
        : "=r"(r0), "=r"(r1), "=r"(r2), "=r"(r3) : "r"(addr))

#define LDSM_X2(r0, r1, addr) \
    asm volatile("ldmatrix.sync.aligned.m8n8.x2.shared.b16 {%0,%1}, [%2];" \
        : "=r"(r0), "=r"(r1) : "r"(addr))

#define MMA_BF16(c, a0, a1, a2, a3, b0, b1) \
    asm volatile("mma.sync.aligned.m16n8k16.row.col.f32.bf16.bf16.f32 " \
        "{%0,%1,%2,%3}, {%4,%5,%6,%7}, {%8,%9}, {%0,%1,%2,%3};" \
        : "+f"((c)[0]), "+f"((c)[1]), "+f"((c)[2]), "+f"((c)[3]) \
        : "r"(a0), "r"(a1), "r"(a2), "r"(a3), "r"(b0), "r"(b1))

#define CP_ASYNC16(dst, src) \
    asm volatile("cp.async.cg.shared.global [%0], [%1], 16;" \
        :: "r"(dst), "l"(src) : "memory")

__global__ __launch_bounds__(256, 2) void proj_mma_kernel(
    const __nv_bfloat16* __restrict__ xh,
    const __nv_bfloat16* __restrict__ xl,
    const __nv_bfloat16* __restrict__ whp,
    const __nv_bfloat16* __restrict__ wlp,
    const float* __restrict__ biasq,
    const float* __restrict__ biask,
    const float* __restrict__ biasv)
{
    extern __shared__ __nv_bfloat16 smem[];
    const uint32_t smb = smem_u32(smem);

    const int tid  = threadIdx.x;
    const int lane = tid & 31;
    const int warp = tid >> 5;
    const int wm   = warp >> 2;        // 0..1 (M)
    const int wn   = warp & 3;         // 0..3 (N)

    const int z  = blockIdx.z;                 // projection 0=Q 1=K 2=V
    const int d0 = blockIdx.y * 128;
    const int n0 = blockIdx.x * 128;

    const __nv_bfloat16* Wh = whp + (size_t)z * CDIM * CDIM;
    const __nv_bfloat16* Wl = wlp + (size_t)z * CDIM * CDIM;

    float acc[4][4][4];
    #pragma unroll
    for (int i = 0; i < 4; ++i)
        #pragma unroll
        for (int j = 0; j < 4; ++j)
            #pragma unroll
            for (int q = 0; q < 4; ++q) acc[i][j][q] = 0.f;

    // per-thread load coordinates: 8 chunks of 16B; mat = i>>1
    const int lr = tid >> 2;           // 0..63 (row half within matrix)
    const int lc = (tid & 3) * 8;      // bf16 col offset of 16B chunk

    // ---- pipelined K loop ----
    #define LOAD_STAGE(s, k0) do { \
        const uint32_t dbase = smb + (s) * STAGE_BYTES + (uint32_t)(lr * TSTRIDE + lc) * 2; \
        const size_t so = (size_t)lr * 512 + (k0) + lc; \
        CP_ASYNC16(dbase,                               Wh + (size_t)d0 * 512 + so); \
        CP_ASYNC16(dbase + 64 * TSTRIDE * 2,            Wh + (size_t)(d0 + 64) * 512 + so); \
        CP_ASYNC16(dbase + TILE_BYTES,                  Wl + (size_t)d0 * 512 + so); \
        CP_ASYNC16(dbase + TILE_BYTES + 64 * TSTRIDE * 2, Wl + (size_t)(d0 + 64) * 512 + so); \
        CP_ASYNC16(dbase + 2 * TILE_BYTES,              xh + (size_t)n0 * 512 + so); \
        CP_ASYNC16(dbase + 2 * TILE_BYTES + 64 * TSTRIDE * 2, xh + (size_t)(n0 + 64) * 512 + so); \
        CP_ASYNC16(dbase + 3 * TILE_BYTES,              xl + (size_t)n0 * 512 + so); \
        CP_ASYNC16(dbase + 3 * TILE_BYTES + 64 * TSTRIDE * 2, xl + (size_t)(n0 + 64) * 512 + so); \
        asm volatile("cp.async.commit_group;" ::: "memory"); \
    } while (0)

    LOAD_STAGE(0, 0);
    LOAD_STAGE(1, 32);

    // precomputed ldmatrix lane offsets
    const int aRow = wm * 64 + (lane & 15);            // + mi*16
    const int aCol = ((lane >> 4) << 3);               // 0 or 8, + kk*16
    const int bRow = wn * 32 + (lane & 7);             // + ni*8
    const int bCol = (((lane >> 3) & 1) << 3);         // 0 or 8, + kk*16

    for (int kt = 0; kt < 16; ++kt) {
        const int s = kt & 1;
        if (kt >= 14) {
            asm volatile("cp.async.wait_group 0;" ::: "memory");
        } else {
            asm volatile("cp.async.wait_group 1;" ::: "memory");
        }
        __syncthreads();

        const uint32_t sA  = smb + s * STAGE_BYTES;
        const uint32_t sB  = sA + 2 * TILE_BYTES;

        #pragma unroll
        for (int kk = 0; kk < 2; ++kk) {
            // B fragments (hi & lo) for all 4 ni
            uint32_t bh[4][2], bl[4][2];
            #pragma unroll
            for (int ni = 0; ni < 4; ++ni) {
                uint32_t ba = sB + (uint32_t)((bRow + ni * 8) * TSTRIDE + kk * 16 + bCol) * 2;
                LDSM_X2(bh[ni][0], bh[ni][1], ba);
                LDSM_X2(bl[ni][0], bl[ni][1], ba + TILE_BYTES);
            }
            #pragma unroll
            for (int mi = 0; mi < 4; ++mi) {
                uint32_t aa = sA + (uint32_t)((aRow + mi * 16) * TSTRIDE + kk * 16 + aCol) * 2;
                uint32_t ah0, ah1, ah2, ah3, al0, al1, al2, al3;
                LDSM_X4(ah0, ah1, ah2, ah3, aa);
                LDSM_X4(al0, al1, al2, al3, aa + TILE_BYTES);
                #pragma unroll
                for (int ni = 0; ni < 4; ++ni) {
                    MMA_BF16(acc[mi][ni], ah0, ah1, ah2, ah3, bh[ni][0], bh[ni][1]);
                    MMA_BF16(acc[mi][ni], ah0, ah1, ah2, ah3, bl[ni][0], bl[ni][1]);
                    MMA_BF16(acc[mi][ni], al0, al1, al2, al3, bh[ni][0], bh[ni][1]);
                }
            }
        }
        __syncthreads();
        if (kt < 14) LOAD_STAGE(s, (kt + 2) * 32);
    }

    // ---- epilogue: bias + sigmoid, channel-major writes ----
    const float* bias = (z == 0) ? biasq : (z == 1) ? biask : biasv;
    float* outp = (z == 0) ? g_Q : (z == 1) ? g_K : g_V;
    const int b  = n0 >> 12;
    const int nb = (n0 & 4095) + wn * 32 + (lane & 3) * 2;

    #pragma unroll
    for (int mi = 0; mi < 4; ++mi) {
        const int dA = d0 + wm * 64 + mi * 16 + (lane >> 2);
        const float bA = bias[dA];
        const float bB = bias[dA + 8];
        float* rowA = outp + (((size_t)(b * 512 + dA)) << 12) + nb;
        float* rowB = rowA + ((size_t)8 << 12);
        #pragma unroll
        for (int ni = 0; ni < 4; ++ni) {
            float2 vA, vB;
            vA.x = 1.f / (1.f + __expf(-(acc[mi][ni][0] + bA)));
            vA.y = 1.f / (1.f + __expf(-(acc[mi][ni][1] + bA)));
            vB.x = 1.f / (1.f + __expf(-(acc[mi][ni][2] + bB)));
            vB.y = 1.f / (1.f + __expf(-(acc[mi][ni][3] + bB)));
            *(float2*)(rowA + ni * 8) = vA;
            *(float2*)(rowB + ni * 8) = vB;
        }
    }
}

// ---------------------------------------------------------------------------
// Attention: one block per (b,c). (unchanged)
// ---------------------------------------------------------------------------
#define S64 65
#define S32 33
#define ATT_SMEM_FLOATS (3 * 64 * S64 + 4 * 32 * S64 + 64 * S32)
#define ATT_SMEM_BYTES (ATT_SMEM_FLOATS * 4)

__global__ __launch_bounds__(256) void attn_kernel(
    const float* __restrict__ gQ,
    const float* __restrict__ gK,
    const float* __restrict__ gV,
    float* __restrict__ gO)
{
    extern __shared__ float sm[];
    float* sQ   = sm;
    float* sK   = sQ   + 64 * S64;
    float* sV   = sK   + 64 * S64;
    float* sq   = sV   + 64 * S64;
    float* sk   = sq   + 32 * S64;
    float* sKq  = sk   + 32 * S64;
    float* sKqv = sKq  + 32 * S64;
    float* sQk  = sKqv + 32 * S64;

    const int bc = blockIdx.x;
    const size_t base = (size_t)bc * 4096;
    const int tid = threadIdx.x;

    for (int idx = tid; idx < 1024; idx += 256) {
        int row = idx >> 4;
        int c4  = (idx & 15) << 2;
        float4 q4 = *(const float4*)(gQ + base + (row << 6) + c4);
        float4 k4 = *(const float4*)(gK + base + (row << 6) + c4);
        float4 v4 = *(const float4*)(gV + base + (row << 6) + c4);
        float* dq = sQ + row * S64 + c4;
        float* dk = sK + row * S64 + c4;
        float* dv = sV + row * S64 + c4;
        dq[0] = q4.x; dq[1] = q4.y; dq[2] = q4.z; dq[3] = q4.w;
        dk[0] = k4.x; dk[1] = k4.y; dk[2] = k4.z; dk[3] = k4.w;
        dv[0] = v4.x; dv[1] = v4.y; dv[2] = v4.z; dv[3] = v4.w;
    }
    __syncthreads();

    for (int idx = tid; idx < 2048; idx += 256) {
        int i  = idx >> 6;
        int ph = idx & 63;
        sq[i * S64 + ph] = 0.5f * (sQ[(2 * i) * S64 + ph] + sQ[(2 * i + 1) * S64 + ph]);
        sk[i * S64 + ph] = 0.5f * (sK[(2 * i) * S64 + ph] + sK[(2 * i + 1) * S64 + ph]);
    }
    __syncthreads();

    const float scale = 0.044194173824159216f;

    {
        const int tr = tid >> 3;
        const int tc = tid & 7;
        float acc[2][4] = {{0.f,0.f,0.f,0.f},{0.f,0.f,0.f,0.f}};
        const float* qr0 = sQ + (2 * tr) * S64;
        const float* qr1 = qr0 + S64;
        #pragma unroll 8
        for (int ph = 0; ph < 64; ++ph) {
            float a0 = qr0[ph], a1 = qr1[ph];
            #pragma unroll
            for (int j = 0; j < 4; ++j) {
                float bb = sk[(4 * tc + j) * S64 + ph];
                acc[0][j] = fmaf(a0, bb, acc[0][j]);
                acc[1][j] = fmaf(a1, bb, acc[1][j]);
            }
        }
        #pragma unroll
        for (int ii = 0; ii < 2; ++ii)
            #pragma unroll
            for (int j = 0; j < 4; ++j)
                sQk[(2 * tr + ii) * S32 + 4 * tc + j] = acc[ii][j] * scale;
    }
    __syncthreads();

    if (tid < 64) {
        float* row = sQk + tid * S32;
        float m = row[0];
        #pragma unroll 8
        for (int j = 1; j < 32; ++j) m = fmaxf(m, row[j]);
        float s = 0.f;
        #pragma unroll 8
        for (int j = 0; j < 32; ++j) { float e = __expf(row[j] - m); row[j] = e; s += e; }
        float inv = 1.f / s;
        #pragma unroll 8
        for (int j = 0; j < 32; ++j) row[j] *= inv;
    }

    {
        const int tr = tid >> 4;
        const int tc = tid & 15;
        float acc[2][4] = {{0.f,0.f,0.f,0.f},{0.f,0.f,0.f,0.f}};
        const float* qr0 = sq + (2 * tr) * S64;
        const float* qr1 = qr0 + S64;
        #pragma unroll 8
        for (int ph = 0; ph < 64; ++ph) {
            float a0 = qr0[ph], a1 = qr1[ph];
            #pragma unroll
            for (int j = 0; j < 4; ++j) {
                float bb = sK[(4 * tc + j) * S64 + ph];
                acc[0][j] = fmaf(a0, bb, acc[0][j]);
                acc[1][j] = fmaf(a1, bb, acc[1][j]);
            }
        }
        #pragma unroll
        for (int ii = 0; ii < 2; ++ii)
            #pragma unroll
            for (int j = 0; j < 4; ++j)
                sKq[(2 * tr + ii) * S64 + 4 * tc + j] = acc[ii][j] * scale;
    }
    __syncthreads();

    if (tid < 32) {
        float* row = sKq + tid * S64;
        float m = row[0];
        #pragma unroll 8
        for (int j = 1; j < 64; ++j) m = fmaxf(m, row[j]);
        float s = 0.f;
        #pragma unroll 8
        for (int j = 0; j < 64; ++j) { float e = __expf(row[j] - m); row[j] = e; s += e; }
        float inv = 1.f / s;
        #pragma unroll 8
        for (int j = 0; j < 64; ++j) row[j] *= inv;
    }
    __syncthreads();

    {
        const int tr = tid >> 4;
        const int tc = tid & 15;
        float acc[2][4] = {{0.f,0.f,0.f,0.f},{0.f,0.f,0.f,0.f}};
        const float* r0 = sKq + (2 * tr) * S64;
        const float* r1 = r0 + S64;
        #pragma unroll 8
        for (int j = 0; j < 64; ++j) {
            float a0 = r0[j], a1 = r1[j];
            #pragma unroll
            for (int jj = 0; jj < 4; ++jj) {
                float bb = sV[j * S64 + 4 * tc + jj];
                acc[0][jj] = fmaf(a0, bb, acc[0][jj]);
                acc[1][jj] = fmaf(a1, bb, acc[1][jj]);
            }
        }
        #pragma unroll
        for (int ii = 0; ii < 2; ++ii)
            #pragma unroll
            for (int jj = 0; jj < 4; ++jj)
                sKqv[(2 * tr + ii) * S64 + 4 * tc + jj] = acc[ii][jj];
    }
    __syncthreads();

    {
        const int tr = tid >> 4;
        const int tc = tid & 15;
        float acc[4][4];
        #pragma unroll
        for (int i = 0; i < 4; ++i)
            #pragma unroll
            for (int j = 0; j < 4; ++j) acc[i][j] = 0.f;
        #pragma unroll 8
        for (int j = 0; j < 32; ++j) {
            float a[4], b[4];
            #pragma unroll
            for (int ii = 0; ii < 4; ++ii) a[ii] = sQk[(4 * tr + ii) * S32 + j];
            #pragma unroll
            for (int jj = 0; jj < 4; ++jj) b[jj] = sKqv[j * S64 + 4 * tc + jj];
            #pragma unroll
            for (int ii = 0; ii < 4; ++ii)
                #pragma unroll
                for (int jj = 0; jj < 4; ++jj)
                    acc[ii][jj] = fmaf(a[ii], b[jj], acc[ii][jj]);
        }
        #pragma unroll
        for (int ii = 0; ii < 4; ++ii) {
            float4 v = make_float4(acc[ii][0], acc[ii][1], acc[ii][2], acc[ii][3]);
            *(float4*)(gO + base + (4 * tr + ii) * 64 + 4 * tc) = v;
        }
    }
}

// ---------------------------------------------------------------------------
// Transpose [B][C][N] -> [B][N][C]
// ---------------------------------------------------------------------------
__global__ __launch_bounds__(256) void transpose_kernel(
    const float* __restrict__ gO, float* __restrict__ out)
{
    __shared__ float tile[32][33];
    const int b  = blockIdx.z;
    const int n0 = blockIdx.x * 32;
    const int c0 = blockIdx.y * 32;
    const float* src = gO + ((size_t)b * 512) * 4096;
    #pragma unroll
    for (int i = threadIdx.y; i < 32; i += 8)
        tile[i][threadIdx.x] = src[(size_t)(c0 + i) * 4096 + n0 + threadIdx.x];
    __syncthreads();
    float* dst = out + ((size_t)b * 4096) * 512;
    #pragma unroll
    for (int i = threadIdx.y; i < 32; i += 8)
        dst[(size_t)(n0 + i) * 512 + c0 + threadIdx.x] = tile[threadIdx.x][i];
}

// ---------------------------------------------------------------------------
// Host side
// ---------------------------------------------------------------------------
extern "C" void kernel_launch(void* const* d_in, const int* in_sizes, int n_in,
                              void* d_out, int out_size)
{
    (void)in_sizes; (void)n_in; (void)out_size;
    const float* x  = (const float*)d_in[0];
    const float* Wq = (const float*)d_in[1];
    const float* bq = (const float*)d_in[2];
    const float* Wk = (const float*)d_in[3];
    const float* bk = (const float*)d_in[4];
    const float* Wv = (const float*)d_in[5];
    const float* bv = (const float*)d_in[6];
    float* out = (float*)d_out;

    float *pQ, *pK, *pV, *pO;
    cudaGetSymbolAddress((void**)&pQ, g_Q);
    cudaGetSymbolAddress((void**)&pK, g_K);
    cudaGetSymbolAddress((void**)&pV, g_V);
    cudaGetSymbolAddress((void**)&pO, g_O);

    __nv_bfloat16 *pxh, *pxl, *pwh, *pwl;
    cudaGetSymbolAddress((void**)&pxh, g_xh);
    cudaGetSymbolAddress((void**)&pxl, g_xl);
    cudaGetSymbolAddress((void**)&pwh, g_wh);
    cudaGetSymbolAddress((void**)&pwl, g_wl);

    // hi/lo splits: x and the three weight matrices
    split_kernel<<<(MTOT * CDIM / 4 + 255) / 256, 256>>>(
        (const float4*)x, (__nv_bfloat162*)pxh, (__nv_bfloat162*)pxl, MTOT * CDIM / 4);
    const float* Ws[3] = {Wq, Wk, Wv};
    for (int i = 0; i < 3; ++i) {
        split_kernel<<<(CDIM * CDIM / 4 + 255) / 256, 256>>>(
            (const float4*)Ws[i],
            (__nv_bfloat162*)(pwh + (size_t)i * CDIM * CDIM),
            (__nv_bfloat162*)(pwl + (size_t)i * CDIM * CDIM),
            CDIM * CDIM / 4);
    }

    cudaFuncSetAttribute(proj_mma_kernel, cudaFuncAttributeMaxDynamicSharedMemorySize,
                         PROJ_SMEM);
    proj_mma_kernel<<<dim3(MTOT / 128, CDIM / 128, 3), 256, PROJ_SMEM>>>(
        pxh, pxl, pwh, pwl, bq, bk, bv);

    cudaFuncSetAttribute(attn_kernel, cudaFuncAttributeMaxDynamicSharedMemorySize,
                         ATT_SMEM_BYTES);
    attn_kernel<<<BATCH * CDIM, 256, ATT_SMEM_BYTES>>>(pQ, pK, pV, pO);

    transpose_kernel<<<dim3(NSEQ / 32, CDIM / 32, BATCH), dim3(32, 8)>>>(pO, out);
}

// round 5
// speedup vs baseline: 2.1673x; 1.0454x over previous
#include <cuda_runtime.h>
#include <cuda_bf16.h>
#include <math.h>
#include <stdint.h>

// ---------------------------------------------------------------------------
// Problem constants
// ---------------------------------------------------------------------------
#define BATCH 16
#define NSEQ 4096
#define CDIM 512
#define MTOT (BATCH * NSEQ)                       // 65536
#define ELEMS ((size_t)BATCH * CDIM * NSEQ)       // 33554432

__device__ float g_Q[ELEMS];
__device__ float g_K[ELEMS];
__device__ float g_V[ELEMS];
__device__ float g_O[ELEMS];

__device__ __nv_bfloat16 g_xh[(size_t)MTOT * CDIM];
__device__ __nv_bfloat16 g_xl[(size_t)MTOT * CDIM];
__device__ __nv_bfloat16 g_wh[3 * CDIM * CDIM];
__device__ __nv_bfloat16 g_wl[3 * CDIM * CDIM];

__device__ __forceinline__ uint32_t smem_u32(const void* p) {
    uint32_t a;
    asm("{ .reg .u64 t; cvta.to.shared.u64 t, %1; cvt.u32.u64 %0, t; }"
        : "=r"(a) : "l"(p));
    return a;
}

// ---------------------------------------------------------------------------
// hi/lo bf16 split kernels
// ---------------------------------------------------------------------------
__device__ __forceinline__ void split4(float4 v, __nv_bfloat162* hi, __nv_bfloat162* lo, int i) {
    __nv_bfloat16 h0 = __float2bfloat16(v.x);
    __nv_bfloat16 h1 = __float2bfloat16(v.y);
    __nv_bfloat16 h2 = __float2bfloat16(v.z);
    __nv_bfloat16 h3 = __float2bfloat16(v.w);
    __nv_bfloat16 l0 = __float2bfloat16(v.x - __bfloat162float(h0));
    __nv_bfloat16 l1 = __float2bfloat16(v.y - __bfloat162float(h1));
    __nv_bfloat16 l2 = __float2bfloat16(v.z - __bfloat162float(h2));
    __nv_bfloat16 l3 = __float2bfloat16(v.w - __bfloat162float(h3));
    hi[2 * i]     = __halves2bfloat162(h0, h1);
    hi[2 * i + 1] = __halves2bfloat162(h2, h3);
    lo[2 * i]     = __halves2bfloat162(l0, l1);
    lo[2 * i + 1] = __halves2bfloat162(l2, l3);
}

__global__ __launch_bounds__(256) void split_kernel(
    const float4* __restrict__ in,
    __nv_bfloat162* __restrict__ hi,
    __nv_bfloat162* __restrict__ lo,
    int n4)
{
    int i = blockIdx.x * 256 + threadIdx.x;
    if (i >= n4) return;
    split4(in[i], hi, lo, i);
}

__global__ __launch_bounds__(256) void splitW_kernel(
    const float4* __restrict__ Wq,
    const float4* __restrict__ Wk,
    const float4* __restrict__ Wv,
    __nv_bfloat162* __restrict__ hi,
    __nv_bfloat162* __restrict__ lo)
{
    const int z = blockIdx.y;
    const float4* src = (z == 0) ? Wq : (z == 1) ? Wk : Wv;
    const int n4 = CDIM * CDIM / 4;
    int i = blockIdx.x * 256 + threadIdx.x;
    if (i >= n4) return;
    split4(src[i], hi + (size_t)z * n4 * 2, lo + (size_t)z * n4 * 2, i);
}

// ---------------------------------------------------------------------------
// Projection GEMM via mma.sync (bf16, fp32 accum), 3-term hi/lo split.
// CTA tile M=128(d) x N=128(n); K in 16-chunks, 4-stage cp.async ring,
// single __syncthreads per iteration. Warps 2(M)x4(N), warp tile 64x32.
// ---------------------------------------------------------------------------
#define PTS 24                         // bf16 per smem row (pad 16->24)
#define PTILE_B (128 * PTS * 2)        // 6144
#define PSTAGE_B (4 * PTILE_B)         // 24576 (Ah,Al,Bh,Bl)
#define PROJ_SMEM (4 * PSTAGE_B)       // 98304

#define LDSM_X4(r0, r1, r2, r3, addr) \
    asm volatile("ldmatrix.sync.aligned.m8n8.x4.shared.b16 {%0,%1,%2,%3}, [%4];" \
        : "=r"(r0), "=r"(r1), "=r"(r2), "=r"(r3) : "r"(addr))

#define MMA_BF16(c, a0, a1, a2, a3, b0, b1) \
    asm volatile("mma.sync.aligned.m16n8k16.row.col.f32.bf16.bf16.f32 " \
        "{%0,%1,%2,%3}, {%4,%5,%6,%7}, {%8,%9}, {%0,%1,%2,%3};" \
        : "+f"((c)[0]), "+f"((c)[1]), "+f"((c)[2]), "+f"((c)[3]) \
        : "r"(a0), "r"(a1), "r"(a2), "r"(a3), "r"(b0), "r"(b1))

#define CP_ASYNC16(dst, src) \
    asm volatile("cp.async.cg.shared.global [%0], [%1], 16;" \
        :: "r"(dst), "l"(src) : "memory")

__global__ __launch_bounds__(256, 2) void proj_mma_kernel(
    const __nv_bfloat16* __restrict__ xh,
    const __nv_bfloat16* __restrict__ xl,
    const __nv_bfloat16* __restrict__ whp,
    const __nv_bfloat16* __restrict__ wlp,
    const float* __restrict__ biasq,
    const float* __restrict__ biask,
    const float* __restrict__ biasv)
{
    extern __shared__ __nv_bfloat16 smem[];
    const uint32_t smb = smem_u32(smem);

    const int tid  = threadIdx.x;
    const int lane = tid & 31;
    const int warp = tid >> 5;
    const int wm   = warp >> 2;
    const int wn   = warp & 3;

    const int z  = blockIdx.z;
    const int d0 = blockIdx.y * 128;
    const int n0 = blockIdx.x * 128;

    const __nv_bfloat16* Wh = whp + (size_t)z * CDIM * CDIM;
    const __nv_bfloat16* Wl = wlp + (size_t)z * CDIM * CDIM;

    float acc[4][4][4];
    #pragma unroll
    for (int i = 0; i < 4; ++i)
        #pragma unroll
        for (int j = 0; j < 4; ++j)
            #pragma unroll
            for (int q = 0; q < 4; ++q) acc[i][j][q] = 0.f;

    // loader coords: 128 rows x 16 k, 16B chunks
    const int lr = tid >> 1;            // 0..127
    const int lc = (tid & 1) * 8;       // 0 or 8

    #define LOAD_STAGE(s, k0) do { \
        const uint32_t db = smb + (s) * PSTAGE_B + (uint32_t)(lr * PTS + lc) * 2; \
        const size_t go = (size_t)lr * 512 + (k0) + lc; \
        CP_ASYNC16(db,               Wh + (size_t)d0 * 512 + go); \
        CP_ASYNC16(db + PTILE_B,     Wl + (size_t)d0 * 512 + go); \
        CP_ASYNC16(db + 2 * PTILE_B, xh + (size_t)n0 * 512 + go); \
        CP_ASYNC16(db + 3 * PTILE_B, xl + (size_t)n0 * 512 + go); \
    } while (0)

    LOAD_STAGE(0, 0);
    asm volatile("cp.async.commit_group;" ::: "memory");
    LOAD_STAGE(1, 16);
    asm volatile("cp.async.commit_group;" ::: "memory");
    LOAD_STAGE(2, 32);
    asm volatile("cp.async.commit_group;" ::: "memory");

    // ldmatrix lane coords
    const int aRow  = wm * 64 + (lane & 15);
    const int aCol  = (lane >> 4) * 8;
    const int g     = lane >> 3;
    const int bRow  = wn * 32 + (g & 2) * 4 + (lane & 7);
    const int bElem = (g & 1) * 8;

    for (int kt = 0; kt < 32; ++kt) {
        asm volatile("cp.async.wait_group 2;" ::: "memory");
        __syncthreads();

        if (kt < 29) LOAD_STAGE((kt + 3) & 3, (kt + 3) * 16);
        asm volatile("cp.async.commit_group;" ::: "memory");

        const uint32_t sS = smb + (kt & 3) * PSTAGE_B;
        const uint32_t sB = sS + 2 * PTILE_B;

        uint32_t bh[4][2], bl[4][2];
        #pragma unroll
        for (int p = 0; p < 2; ++p) {
            uint32_t ba = sB + (uint32_t)((bRow + p * 16) * PTS + bElem) * 2;
            LDSM_X4(bh[2 * p][0], bh[2 * p][1], bh[2 * p + 1][0], bh[2 * p + 1][1], ba);
            LDSM_X4(bl[2 * p][0], bl[2 * p][1], bl[2 * p + 1][0], bl[2 * p + 1][1], ba + PTILE_B);
        }

        #pragma unroll
        for (int mi = 0; mi < 4; ++mi) {
            uint32_t aa = sS + (uint32_t)((aRow + mi * 16) * PTS + aCol) * 2;
            uint32_t ah0, ah1, ah2, ah3, al0, al1, al2, al3;
            LDSM_X4(ah0, ah1, ah2, ah3, aa);
            LDSM_X4(al0, al1, al2, al3, aa + PTILE_B);
            #pragma unroll
            for (int ni = 0; ni < 4; ++ni) {
                MMA_BF16(acc[mi][ni], ah0, ah1, ah2, ah3, bh[ni][0], bh[ni][1]);
                MMA_BF16(acc[mi][ni], ah0, ah1, ah2, ah3, bl[ni][0], bl[ni][1]);
                MMA_BF16(acc[mi][ni], al0, al1, al2, al3, bh[ni][0], bh[ni][1]);
            }
        }
    }

    // epilogue: bias + sigmoid, channel-major writes
    const float* bias = (z == 0) ? biasq : (z == 1) ? biask : biasv;
    float* outp = (z == 0) ? g_Q : (z == 1) ? g_K : g_V;
    const int b  = n0 >> 12;
    const int nb = (n0 & 4095) + wn * 32 + (lane & 3) * 2;

    #pragma unroll
    for (int mi = 0; mi < 4; ++mi) {
        const int dA = d0 + wm * 64 + mi * 16 + (lane >> 2);
        const float bA = bias[dA];
        const float bB = bias[dA + 8];
        float* rowA = outp + (((size_t)(b * 512 + dA)) << 12) + nb;
        float* rowB = rowA + ((size_t)8 << 12);
        #pragma unroll
        for (int ni = 0; ni < 4; ++ni) {
            float2 vA, vB;
            vA.x = 1.f / (1.f + __expf(-(acc[mi][ni][0] + bA)));
            vA.y = 1.f / (1.f + __expf(-(acc[mi][ni][1] + bA)));
            vB.x = 1.f / (1.f + __expf(-(acc[mi][ni][2] + bB)));
            vB.y = 1.f / (1.f + __expf(-(acc[mi][ni][3] + bB)));
            *(float2*)(rowA + ni * 8) = vA;
            *(float2*)(rowB + ni * 8) = vB;
        }
    }
}

// ---------------------------------------------------------------------------
// Attention: one block per (b,c), fully float4-vectorized smem matmuls +
// warp-shuffle softmax. Strides: 68 floats (big mats), 36 (Qk).
// ---------------------------------------------------------------------------
#define S68 68
#define S36 36
#define ATT_SMEM_FLOATS (3 * 64 * S68 + 4 * 32 * S68 + 64 * S36)   // 24064
#define ATT_SMEM_BYTES (ATT_SMEM_FLOATS * 4)                        // 96256

__global__ __launch_bounds__(256, 2) void attn_kernel(
    const float* __restrict__ gQ,
    const float* __restrict__ gK,
    const float* __restrict__ gV,
    float* __restrict__ gO)
{
    extern __shared__ float sm[];
    float* sQ   = sm;
    float* sK   = sQ   + 64 * S68;
    float* sV   = sK   + 64 * S68;
    float* sq   = sV   + 64 * S68;
    float* sk   = sq   + 32 * S68;
    float* sKq  = sk   + 32 * S68;
    float* sKqv = sKq  + 32 * S68;
    float* sQk  = sKqv + 32 * S68;

    const int bc = blockIdx.x;
    const size_t base = (size_t)bc * 4096;
    const int tid = threadIdx.x;

    // load Q,K,V (64x64 each), stride-68 smem
    for (int idx = tid; idx < 1024; idx += 256) {
        int row = idx >> 4;
        int c4  = (idx & 15) << 2;
        float4 q4 = *(const float4*)(gQ + base + (row << 6) + c4);
        float4 k4 = *(const float4*)(gK + base + (row << 6) + c4);
        float4 v4 = *(const float4*)(gV + base + (row << 6) + c4);
        *(float4*)(sQ + row * S68 + c4) = q4;
        *(float4*)(sK + row * S68 + c4) = k4;
        *(float4*)(sV + row * S68 + c4) = v4;
    }
    __syncthreads();

    // pool over PW (row pairs), vectorized
    for (int idx = tid; idx < 512; idx += 256) {
        int i = idx >> 4;
        int c = (idx & 15) << 2;
        float4 a = *(float4*)(sQ + (2 * i) * S68 + c);
        float4 b = *(float4*)(sQ + (2 * i + 1) * S68 + c);
        float4 r = make_float4(0.5f * (a.x + b.x), 0.5f * (a.y + b.y),
                               0.5f * (a.z + b.z), 0.5f * (a.w + b.w));
        *(float4*)(sq + i * S68 + c) = r;
        a = *(float4*)(sK + (2 * i) * S68 + c);
        b = *(float4*)(sK + (2 * i + 1) * S68 + c);
        r = make_float4(0.5f * (a.x + b.x), 0.5f * (a.y + b.y),
                        0.5f * (a.z + b.z), 0.5f * (a.w + b.w));
        *(float4*)(sk + i * S68 + c) = r;
    }
    __syncthreads();

    const float scale = 0.044194173824159216f;   // 1/sqrt(512)

    // S1: Qk[i][j] = scale * sum_ph Q[i][ph]*k[j][ph]  (64x32)
    {
        const int tr = tid >> 3;       // rows 2tr, 2tr+1
        const int tc = tid & 7;        // cols tc + 8j
        float a0s[4], a1s[4];
        (void)a0s; (void)a1s;
        float acc[2][4] = {{0,0,0,0},{0,0,0,0}};
        const float* qr0 = sQ + (2 * tr) * S68;
        const float* qr1 = qr0 + S68;
        #pragma unroll
        for (int p4 = 0; p4 < 16; ++p4) {
            float4 a0 = *(const float4*)(qr0 + p4 * 4);
            float4 a1 = *(const float4*)(qr1 + p4 * 4);
            #pragma unroll
            for (int j = 0; j < 4; ++j) {
                float4 b = *(const float4*)(sk + (tc + 8 * j) * S68 + p4 * 4);
                acc[0][j] += a0.x * b.x + a0.y * b.y + a0.z * b.z + a0.w * b.w;
                acc[1][j] += a1.x * b.x + a1.y * b.y + a1.z * b.z + a1.w * b.w;
            }
        }
        #pragma unroll
        for (int ii = 0; ii < 2; ++ii)
            #pragma unroll
            for (int j = 0; j < 4; ++j)
                sQk[(2 * tr + ii) * S36 + tc + 8 * j] = acc[ii][j] * scale;
    }
    __syncthreads();

    // softmax rows of sQk (64x32): 4 lanes per row, 8 elems each
    {
        const int row = tid >> 2;
        const int s   = tid & 3;
        float* rp = sQk + row * S36 + s * 8;
        float4 v0 = *(float4*)rp;
        float4 v1 = *(float4*)(rp + 4);
        float m = fmaxf(fmaxf(fmaxf(v0.x, v0.y), fmaxf(v0.z, v0.w)),
                        fmaxf(fmaxf(v1.x, v1.y), fmaxf(v1.z, v1.w)));
        m = fmaxf(m, __shfl_xor_sync(0xffffffffu, m, 1));
        m = fmaxf(m, __shfl_xor_sync(0xffffffffu, m, 2));
        v0.x = __expf(v0.x - m); v0.y = __expf(v0.y - m);
        v0.z = __expf(v0.z - m); v0.w = __expf(v0.w - m);
        v1.x = __expf(v1.x - m); v1.y = __expf(v1.y - m);
        v1.z = __expf(v1.z - m); v1.w = __expf(v1.w - m);
        float su = v0.x + v0.y + v0.z + v0.w + v1.x + v1.y + v1.z + v1.w;
        su += __shfl_xor_sync(0xffffffffu, su, 1);
        su += __shfl_xor_sync(0xffffffffu, su, 2);
        float inv = 1.f / su;
        v0.x *= inv; v0.y *= inv; v0.z *= inv; v0.w *= inv;
        v1.x *= inv; v1.y *= inv; v1.z *= inv; v1.w *= inv;
        *(float4*)rp = v0;
        *(float4*)(rp + 4) = v1;
    }

    // S2: Kq[i][j] = scale * sum_ph q[i][ph]*K[j][ph]  (32x64)
    {
        const int tr = tid >> 4;       // rows 2tr, 2tr+1
        const int tc = tid & 15;       // cols tc + 16j
        float acc[2][4] = {{0,0,0,0},{0,0,0,0}};
        const float* qr0 = sq + (2 * tr) * S68;
        const float* qr1 = qr0 + S68;
        #pragma unroll
        for (int p4 = 0; p4 < 16; ++p4) {
            float4 a0 = *(const float4*)(qr0 + p4 * 4);
            float4 a1 = *(const float4*)(qr1 + p4 * 4);
            #pragma unroll
            for (int j = 0; j < 4; ++j) {
                float4 b = *(const float4*)(sK + (tc + 16 * j) * S68 + p4 * 4);
                acc[0][j] += a0.x * b.x + a0.y * b.y + a0.z * b.z + a0.w * b.w;
                acc[1][j] += a1.x * b.x + a1.y * b.y + a1.z * b.z + a1.w * b.w;
            }
        }
        #pragma unroll
        for (int ii = 0; ii < 2; ++ii)
            #pragma unroll
            for (int j = 0; j < 4; ++j)
                sKq[(2 * tr + ii) * S68 + tc + 16 * j] = acc[ii][j] * scale;
    }
    __syncthreads();

    // softmax rows of sKq (32x64): 8 lanes per row, 8 elems each
    {
        const int row = tid >> 3;
        const int s   = tid & 7;
        float* rp = sKq + row * S68 + s * 8;
        float4 v0 = *(float4*)rp;
        float4 v1 = *(float4*)(rp + 4);
        float m = fmaxf(fmaxf(fmaxf(v0.x, v0.y), fmaxf(v0.z, v0.w)),
                        fmaxf(fmaxf(v1.x, v1.y), fmaxf(v1.z, v1.w)));
        m = fmaxf(m, __shfl_xor_sync(0xffffffffu, m, 1));
        m = fmaxf(m, __shfl_xor_sync(0xffffffffu, m, 2));
        m = fmaxf(m, __shfl_xor_sync(0xffffffffu, m, 4));
        v0.x = __expf(v0.x - m); v0.y = __expf(v0.y - m);
        v0.z = __expf(v0.z - m); v0.w = __expf(v0.w - m);
        v1.x = __expf(v1.x - m); v1.y = __expf(v1.y - m);
        v1.z = __expf(v1.z - m); v1.w = __expf(v1.w - m);
        float su = v0.x + v0.y + v0.z + v0.w + v1.x + v1.y + v1.z + v1.w;
        su += __shfl_xor_sync(0xffffffffu, su, 1);
        su += __shfl_xor_sync(0xffffffffu, su, 2);
        su += __shfl_xor_sync(0xffffffffu, su, 4);
        float inv = 1.f / su;
        v0.x *= inv; v0.y *= inv; v0.z *= inv; v0.w *= inv;
        v1.x *= inv; v1.y *= inv; v1.z *= inv; v1.w *= inv;
        *(float4*)rp = v0;
        *(float4*)(rp + 4) = v1;
    }
    __syncthreads();

    // S3: Kqv[i][ph] = sum_j Kq[i][j]*V[j][ph]  (32x64, contract 64)
    {
        const int tr = tid >> 4;       // rows 2tr, 2tr+1
        const int tc = tid & 15;       // cols 4tc..4tc+3
        float4 acc0 = make_float4(0, 0, 0, 0);
        float4 acc1 = make_float4(0, 0, 0, 0);
        const float* r0 = sKq + (2 * tr) * S68;
        const float* r1 = r0 + S68;
        #pragma unroll
        for (int j4 = 0; j4 < 16; ++j4) {
            float4 a0 = *(const float4*)(r0 + j4 * 4);
            float4 a1 = *(const float4*)(r1 + j4 * 4);
            const float* vb = sV + (j4 * 4) * S68 + 4 * tc;
            float4 b0 = *(const float4*)(vb);
            float4 b1 = *(const float4*)(vb + S68);
            float4 b2 = *(const float4*)(vb + 2 * S68);
            float4 b3 = *(const float4*)(vb + 3 * S68);
            acc0.x += a0.x * b0.x + a0.y * b1.x + a0.z * b2.x + a0.w * b3.x;
            acc0.y += a0.x * b0.y + a0.y * b1.y + a0.z * b2.y + a0.w * b3.y;
            acc0.z += a0.x * b0.z + a0.y * b1.z + a0.z * b2.z + a0.w * b3.z;
            acc0.w += a0.x * b0.w + a0.y * b1.w + a0.z * b2.w + a0.w * b3.w;
            acc1.x += a1.x * b0.x + a1.y * b1.x + a1.z * b2.x + a1.w * b3.x;
            acc1.y += a1.x * b0.y + a1.y * b1.y + a1.z * b2.y + a1.w * b3.y;
            acc1.z += a1.x * b0.z + a1.y * b1.z + a1.z * b2.z + a1.w * b3.z;
            acc1.w += a1.x * b0.w + a1.y * b1.w + a1.z * b2.w + a1.w * b3.w;
        }
        *(float4*)(sKqv + (2 * tr) * S68 + 4 * tc) = acc0;
        *(float4*)(sKqv + (2 * tr + 1) * S68 + 4 * tc) = acc1;
    }
    __syncthreads();

    // S4: out[i][ph] = sum_j Qk[i][j]*Kqv[j][ph]  (64x64, contract 32)
    {
        const int tr = tid >> 4;       // rows 4tr..4tr+3
        const int tc = tid & 15;       // cols 4tc..4tc+3
        float4 acc[4];
        #pragma unroll
        for (int i = 0; i < 4; ++i) acc[i] = make_float4(0, 0, 0, 0);
        #pragma unroll
        for (int j4 = 0; j4 < 8; ++j4) {
            float4 a[4];
            #pragma unroll
            for (int ii = 0; ii < 4; ++ii)
                a[ii] = *(const float4*)(sQk + (4 * tr + ii) * S36 + j4 * 4);
            const float* kb = sKqv + (j4 * 4) * S68 + 4 * tc;
            float4 b0 = *(const float4*)(kb);
            float4 b1 = *(const float4*)(kb + S68);
            float4 b2 = *(const float4*)(kb + 2 * S68);
            float4 b3 = *(const float4*)(kb + 3 * S68);
            #pragma unroll
            for (int ii = 0; ii < 4; ++ii) {
                acc[ii].x += a[ii].x * b0.x + a[ii].y * b1.x + a[ii].z * b2.x + a[ii].w * b3.x;
                acc[ii].y += a[ii].x * b0.y + a[ii].y * b1.y + a[ii].z * b2.y + a[ii].w * b3.y;
                acc[ii].z += a[ii].x * b0.z + a[ii].y * b1.z + a[ii].z * b2.z + a[ii].w * b3.z;
                acc[ii].w += a[ii].x * b0.w + a[ii].y * b1.w + a[ii].z * b2.w + a[ii].w * b3.w;
            }
        }
        #pragma unroll
        for (int ii = 0; ii < 4; ++ii)
            *(float4*)(gO + base + (4 * tr + ii) * 64 + 4 * tc) = acc[ii];
    }
}

// ---------------------------------------------------------------------------
// Transpose [B][C][N] -> [B][N][C]
// ---------------------------------------------------------------------------
__global__ __launch_bounds__(256) void transpose_kernel(
    const float* __restrict__ gO, float* __restrict__ out)
{
    __shared__ float tile[32][33];
    const int b  = blockIdx.z;
    const int n0 = blockIdx.x * 32;
    const int c0 = blockIdx.y * 32;
    const float* src = gO + ((size_t)b * 512) * 4096;
    #pragma unroll
    for (int i = threadIdx.y; i < 32; i += 8)
        tile[i][threadIdx.x] = src[(size_t)(c0 + i) * 4096 + n0 + threadIdx.x];
    __syncthreads();
    float* dst = out + ((size_t)b * 4096) * 512;
    #pragma unroll
    for (int i = threadIdx.y; i < 32; i += 8)
        dst[(size_t)(n0 + i) * 512 + c0 + threadIdx.x] = tile[threadIdx.x][i];
}

// ---------------------------------------------------------------------------
// Host side
// ---------------------------------------------------------------------------
extern "C" void kernel_launch(void* const* d_in, const int* in_sizes, int n_in,
                              void* d_out, int out_size)
{
    (void)in_sizes; (void)n_in; (void)out_size;
    const float* x  = (const float*)d_in[0];
    const float* Wq = (const float*)d_in[1];
    const float* bq = (const float*)d_in[2];
    const float* Wk = (const float*)d_in[3];
    const float* bk = (const float*)d_in[4];
    const float* Wv = (const float*)d_in[5];
    const float* bv = (const float*)d_in[6];
    float* out = (float*)d_out;

    float *pQ, *pK, *pV, *pO;
    cudaGetSymbolAddress((void**)&pQ, g_Q);
    cudaGetSymbolAddress((void**)&pK, g_K);
    cudaGetSymbolAddress((void**)&pV, g_V);
    cudaGetSymbolAddress((void**)&pO, g_O);

    __nv_bfloat16 *pxh, *pxl, *pwh, *pwl;
    cudaGetSymbolAddress((void**)&pxh, g_xh);
    cudaGetSymbolAddress((void**)&pxl, g_xl);
    cudaGetSymbolAddress((void**)&pwh, g_wh);
    cudaGetSymbolAddress((void**)&pwl, g_wl);

    // hi/lo splits
    split_kernel<<<(MTOT * CDIM / 4 + 255) / 256, 256>>>(
        (const float4*)x, (__nv_bfloat162*)pxh, (__nv_bfloat162*)pxl, MTOT * CDIM / 4);
    splitW_kernel<<<dim3((CDIM * CDIM / 4 + 255) / 256, 3), 256>>>(
        (const float4*)Wq, (const float4*)Wk, (const float4*)Wv,
        (__nv_bfloat162*)pwh, (__nv_bfloat162*)pwl);

    cudaFuncSetAttribute(proj_mma_kernel, cudaFuncAttributeMaxDynamicSharedMemorySize,
                         PROJ_SMEM);
    proj_mma_kernel<<<dim3(MTOT / 128, CDIM / 128, 3), 256, PROJ_SMEM>>>(
        pxh, pxl, pwh, pwl, bq, bk, bv);

    cudaFuncSetAttribute(attn_kernel, cudaFuncAttributeMaxDynamicSharedMemorySize,
                         ATT_SMEM_BYTES);
    attn_kernel<<<BATCH * CDIM, 256, ATT_SMEM_BYTES>>>(pQ, pK, pV, pO);

    transpose_kernel<<<dim3(NSEQ / 32, CDIM / 32, BATCH), dim3(32, 8)>>>(pO, out);
}

// round 6
// speedup vs baseline: 3.4921x; 1.6113x over previous
#include <cuda_runtime.h>
#include <cuda_fp16.h>
#include <math.h>
#include <stdint.h>

// ---------------------------------------------------------------------------
// Problem constants
// ---------------------------------------------------------------------------
#define BATCH 16
#define NSEQ 4096
#define CDIM 512
#define MTOT (BATCH * NSEQ)                       // 65536
#define ELEMS ((size_t)BATCH * CDIM * NSEQ)       // 33554432

__device__ float g_Q[ELEMS];
__device__ float g_K[ELEMS];
__device__ float g_V[ELEMS];
__device__ float g_O[ELEMS];

__device__ __half g_xh[(size_t)MTOT * CDIM];      // fp16 x
__device__ __half g_wh[3 * CDIM * CDIM];          // fp16 W (q,k,v)

__device__ __forceinline__ uint32_t smem_u32(const void* p) {
    uint32_t a;
    asm("{ .reg .u64 t; cvta.to.shared.u64 t, %1; cvt.u32.u64 %0, t; }"
        : "=r"(a) : "l"(p));
    return a;
}

// ---------------------------------------------------------------------------
// fp32 -> fp16 conversion kernels
// ---------------------------------------------------------------------------
__global__ __launch_bounds__(256) void convX_kernel(
    const float4* __restrict__ in, __half2* __restrict__ outp, int n4)
{
    int i = blockIdx.x * 256 + threadIdx.x;
    if (i >= n4) return;
    float4 v = in[i];
    outp[2 * i]     = __floats2half2_rn(v.x, v.y);
    outp[2 * i + 1] = __floats2half2_rn(v.z, v.w);
}

__global__ __launch_bounds__(256) void convW_kernel(
    const float4* __restrict__ Wq,
    const float4* __restrict__ Wk,
    const float4* __restrict__ Wv,
    __half2* __restrict__ outp)
{
    const int z = blockIdx.y;
    const float4* src = (z == 0) ? Wq : (z == 1) ? Wk : Wv;
    const int n4 = CDIM * CDIM / 4;
    int i = blockIdx.x * 256 + threadIdx.x;
    if (i >= n4) return;
    float4 v = src[i];
    __half2* o = outp + (size_t)z * n4 * 2;
    o[2 * i]     = __floats2half2_rn(v.x, v.y);
    o[2 * i + 1] = __floats2half2_rn(v.z, v.w);
}

// ---------------------------------------------------------------------------
// Projection GEMM via mma.sync (fp16, fp32 accum), single term.
// CTA tile M=128(d) x N=128(n); K in 32-chunks, 16 iters, 4-stage cp.async.
// Warps 2(M)x4(N); warp tile 64x32; m16n8k16.
// ---------------------------------------------------------------------------
#define PTS 40                          // half per smem row (pad 32->40)
#define PTILE_B (128 * PTS * 2)         // 10240 bytes
#define PSTAGE_B (2 * PTILE_B)          // 20480 (A, B)
#define PROJ_SMEM (4 * PSTAGE_B)        // 81920

#define LDSM_X4(r0, r1, r2, r3, addr) \
    asm volatile("ldmatrix.sync.aligned.m8n8.x4.shared.b16 {%0,%1,%2,%3}, [%4];" \
        : "=r"(r0), "=r"(r1), "=r"(r2), "=r"(r3) : "r"(addr))

#define MMA_F16(c, a0, a1, a2, a3, b0, b1) \
    asm volatile("mma.sync.aligned.m16n8k16.row.col.f32.f16.f16.f32 " \
        "{%0,%1,%2,%3}, {%4,%5,%6,%7}, {%8,%9}, {%0,%1,%2,%3};" \
        : "+f"((c)[0]), "+f"((c)[1]), "+f"((c)[2]), "+f"((c)[3]) \
        : "r"(a0), "r"(a1), "r"(a2), "r"(a3), "r"(b0), "r"(b1))

#define CP_ASYNC16(dst, src) \
    asm volatile("cp.async.cg.shared.global [%0], [%1], 16;" \
        :: "r"(dst), "l"(src) : "memory")

__global__ __launch_bounds__(256, 2) void proj_mma_kernel(
    const __half* __restrict__ xh,
    const __half* __restrict__ whp,
    const float* __restrict__ biasq,
    const float* __restrict__ biask,
    const float* __restrict__ biasv)
{
    extern __shared__ __half smem[];
    const uint32_t smb = smem_u32(smem);

    const int tid  = threadIdx.x;
    const int lane = tid & 31;
    const int warp = tid >> 5;
    const int wm   = warp >> 2;
    const int wn   = warp & 3;

    const int z  = blockIdx.z;
    const int d0 = blockIdx.y * 128;
    const int n0 = blockIdx.x * 128;

    const __half* W = whp + (size_t)z * CDIM * CDIM;

    float acc[4][4][4];
    #pragma unroll
    for (int i = 0; i < 4; ++i)
        #pragma unroll
        for (int j = 0; j < 4; ++j)
            #pragma unroll
            for (int q = 0; q < 4; ++q) acc[i][j][q] = 0.f;

    // loader coords: 128 rows x 32 k per tile; 2 threads/row, 2 chunks each
    const int lr = tid >> 1;              // 0..127
    const int lc = (tid & 1) * 16;        // 0 or 16 (half elems)

    #define LOAD_STAGE(s, k0) do { \
        const uint32_t db = smb + (s) * PSTAGE_B + (uint32_t)(lr * PTS + lc) * 2; \
        const size_t go = (size_t)lr * 512 + (k0) + lc; \
        CP_ASYNC16(db,                W + (size_t)d0 * 512 + go); \
        CP_ASYNC16(db + 16,           W + (size_t)d0 * 512 + go + 8); \
        CP_ASYNC16(db + PTILE_B,      xh + (size_t)n0 * 512 + go); \
        CP_ASYNC16(db + PTILE_B + 16, xh + (size_t)n0 * 512 + go + 8); \
    } while (0)

    LOAD_STAGE(0, 0);
    asm volatile("cp.async.commit_group;" ::: "memory");
    LOAD_STAGE(1, 32);
    asm volatile("cp.async.commit_group;" ::: "memory");
    LOAD_STAGE(2, 64);
    asm volatile("cp.async.commit_group;" ::: "memory");

    // ldmatrix lane coords
    const int aRow  = wm * 64 + (lane & 15);
    const int aCol  = (lane >> 4) * 8;
    const int g     = lane >> 3;
    const int bRow  = wn * 32 + (g & 2) * 4 + (lane & 7);
    const int bElem = (g & 1) * 8;

    for (int kt = 0; kt < 16; ++kt) {
        asm volatile("cp.async.wait_group 2;" ::: "memory");
        __syncthreads();

        if (kt < 13) LOAD_STAGE((kt + 3) & 3, (kt + 3) * 32);
        asm volatile("cp.async.commit_group;" ::: "memory");

        const uint32_t sA = smb + (kt & 3) * PSTAGE_B;
        const uint32_t sB = sA + PTILE_B;

        #pragma unroll
        for (int kk = 0; kk < 2; ++kk) {
            uint32_t bh[4][2];
            #pragma unroll
            for (int p = 0; p < 2; ++p) {
                uint32_t ba = sB + (uint32_t)((bRow + p * 16) * PTS + kk * 16 + bElem) * 2;
                LDSM_X4(bh[2 * p][0], bh[2 * p][1], bh[2 * p + 1][0], bh[2 * p + 1][1], ba);
            }
            #pragma unroll
            for (int mi = 0; mi < 4; ++mi) {
                uint32_t aa = sA + (uint32_t)((aRow + mi * 16) * PTS + kk * 16 + aCol) * 2;
                uint32_t a0, a1, a2, a3;
                LDSM_X4(a0, a1, a2, a3, aa);
                #pragma unroll
                for (int ni = 0; ni < 4; ++ni)
                    MMA_F16(acc[mi][ni], a0, a1, a2, a3, bh[ni][0], bh[ni][1]);
            }
        }
    }

    // epilogue: bias + sigmoid, channel-major writes
    const float* bias = (z == 0) ? biasq : (z == 1) ? biask : biasv;
    float* outp = (z == 0) ? g_Q : (z == 1) ? g_K : g_V;
    const int b  = n0 >> 12;
    const int nb = (n0 & 4095) + wn * 32 + (lane & 3) * 2;

    #pragma unroll
    for (int mi = 0; mi < 4; ++mi) {
        const int dA = d0 + wm * 64 + mi * 16 + (lane >> 2);
        const float bA = bias[dA];
        const float bB = bias[dA + 8];
        float* rowA = outp + (((size_t)(b * 512 + dA)) << 12) + nb;
        float* rowB = rowA + ((size_t)8 << 12);
        #pragma unroll
        for (int ni = 0; ni < 4; ++ni) {
            float2 vA, vB;
            vA.x = 1.f / (1.f + __expf(-(acc[mi][ni][0] + bA)));
            vA.y = 1.f / (1.f + __expf(-(acc[mi][ni][1] + bA)));
            vB.x = 1.f / (1.f + __expf(-(acc[mi][ni][2] + bB)));
            vB.y = 1.f / (1.f + __expf(-(acc[mi][ni][3] + bB)));
            *(float2*)(rowA + ni * 8) = vA;
            *(float2*)(rowB + ni * 8) = vB;
        }
    }
}

// ---------------------------------------------------------------------------
// Attention: one block per (b,c), float4-vectorized smem matmuls +
// warp-shuffle softmax. (unchanged from round 5 — 330us, LDS-bound)
// ---------------------------------------------------------------------------
#define S68 68
#define S36 36
#define ATT_SMEM_FLOATS (3 * 64 * S68 + 4 * 32 * S68 + 64 * S36)
#define ATT_SMEM_BYTES (ATT_SMEM_FLOATS * 4)

__global__ __launch_bounds__(256, 2) void attn_kernel(
    const float* __restrict__ gQ,
    const float* __restrict__ gK,
    const float* __restrict__ gV,
    float* __restrict__ gO)
{
    extern __shared__ float sm[];
    float* sQ   = sm;
    float* sK   = sQ   + 64 * S68;
    float* sV   = sK   + 64 * S68;
    float* sq   = sV   + 64 * S68;
    float* sk   = sq   + 32 * S68;
    float* sKq  = sk   + 32 * S68;
    float* sKqv = sKq  + 32 * S68;
    float* sQk  = sKqv + 32 * S68;

    const int bc = blockIdx.x;
    const size_t base = (size_t)bc * 4096;
    const int tid = threadIdx.x;

    for (int idx = tid; idx < 1024; idx += 256) {
        int row = idx >> 4;
        int c4  = (idx & 15) << 2;
        float4 q4 = *(const float4*)(gQ + base + (row << 6) + c4);
        float4 k4 = *(const float4*)(gK + base + (row << 6) + c4);
        float4 v4 = *(const float4*)(gV + base + (row << 6) + c4);
        *(float4*)(sQ + row * S68 + c4) = q4;
        *(float4*)(sK + row * S68 + c4) = k4;
        *(float4*)(sV + row * S68 + c4) = v4;
    }
    __syncthreads();

    for (int idx = tid; idx < 512; idx += 256) {
        int i = idx >> 4;
        int c = (idx & 15) << 2;
        float4 a = *(float4*)(sQ + (2 * i) * S68 + c);
        float4 b = *(float4*)(sQ + (2 * i + 1) * S68 + c);
        float4 r = make_float4(0.5f * (a.x + b.x), 0.5f * (a.y + b.y),
                               0.5f * (a.z + b.z), 0.5f * (a.w + b.w));
        *(float4*)(sq + i * S68 + c) = r;
        a = *(float4*)(sK + (2 * i) * S68 + c);
        b = *(float4*)(sK + (2 * i + 1) * S68 + c);
        r = make_float4(0.5f * (a.x + b.x), 0.5f * (a.y + b.y),
                        0.5f * (a.z + b.z), 0.5f * (a.w + b.w));
        *(float4*)(sk + i * S68 + c) = r;
    }
    __syncthreads();

    const float scale = 0.044194173824159216f;

    // S1: Qk = scale * Q @ k^T (64x32)
    {
        const int tr = tid >> 3;
        const int tc = tid & 7;
        float acc[2][4] = {{0,0,0,0},{0,0,0,0}};
        const float* qr0 = sQ + (2 * tr) * S68;
        const float* qr1 = qr0 + S68;
        #pragma unroll
        for (int p4 = 0; p4 < 16; ++p4) {
            float4 a0 = *(const float4*)(qr0 + p4 * 4);
            float4 a1 = *(const float4*)(qr1 + p4 * 4);
            #pragma unroll
            for (int j = 0; j < 4; ++j) {
                float4 b = *(const float4*)(sk + (tc + 8 * j) * S68 + p4 * 4);
                acc[0][j] += a0.x * b.x + a0.y * b.y + a0.z * b.z + a0.w * b.w;
                acc[1][j] += a1.x * b.x + a1.y * b.y + a1.z * b.z + a1.w * b.w;
            }
        }
        #pragma unroll
        for (int ii = 0; ii < 2; ++ii)
            #pragma unroll
            for (int j = 0; j < 4; ++j)
                sQk[(2 * tr + ii) * S36 + tc + 8 * j] = acc[ii][j] * scale;
    }
    __syncthreads();

    // softmax rows of sQk (64x32)
    {
        const int row = tid >> 2;
        const int s   = tid & 3;
        float* rp = sQk + row * S36 + s * 8;
        float4 v0 = *(float4*)rp;
        float4 v1 = *(float4*)(rp + 4);
        float m = fmaxf(fmaxf(fmaxf(v0.x, v0.y), fmaxf(v0.z, v0.w)),
                        fmaxf(fmaxf(v1.x, v1.y), fmaxf(v1.z, v1.w)));
        m = fmaxf(m, __shfl_xor_sync(0xffffffffu, m, 1));
        m = fmaxf(m, __shfl_xor_sync(0xffffffffu, m, 2));
        v0.x = __expf(v0.x - m); v0.y = __expf(v0.y - m);
        v0.z = __expf(v0.z - m); v0.w = __expf(v0.w - m);
        v1.x = __expf(v1.x - m); v1.y = __expf(v1.y - m);
        v1.z = __expf(v1.z - m); v1.w = __expf(v1.w - m);
        float su = v0.x + v0.y + v0.z + v0.w + v1.x + v1.y + v1.z + v1.w;
        su += __shfl_xor_sync(0xffffffffu, su, 1);
        su += __shfl_xor_sync(0xffffffffu, su, 2);
        float inv = 1.f / su;
        v0.x *= inv; v0.y *= inv; v0.z *= inv; v0.w *= inv;
        v1.x *= inv; v1.y *= inv; v1.z *= inv; v1.w *= inv;
        *(float4*)rp = v0;
        *(float4*)(rp + 4) = v1;
    }

    // S2: Kq = scale * q @ K^T (32x64)
    {
        const int tr = tid >> 4;
        const int tc = tid & 15;
        float acc[2][4] = {{0,0,0,0},{0,0,0,0}};
        const float* qr0 = sq + (2 * tr) * S68;
        const float* qr1 = qr0 + S68;
        #pragma unroll
        for (int p4 = 0; p4 < 16; ++p4) {
            float4 a0 = *(const float4*)(qr0 + p4 * 4);
            float4 a1 = *(const float4*)(qr1 + p4 * 4);
            #pragma unroll
            for (int j = 0; j < 4; ++j) {
                float4 b = *(const float4*)(sK + (tc + 16 * j) * S68 + p4 * 4);
                acc[0][j] += a0.x * b.x + a0.y * b.y + a0.z * b.z + a0.w * b.w;
                acc[1][j] += a1.x * b.x + a1.y * b.y + a1.z * b.z + a1.w * b.w;
            }
        }
        #pragma unroll
        for (int ii = 0; ii < 2; ++ii)
            #pragma unroll
            for (int j = 0; j < 4; ++j)
                sKq[(2 * tr + ii) * S68 + tc + 16 * j] = acc[ii][j] * scale;
    }
    __syncthreads();

    // softmax rows of sKq (32x64)
    {
        const int row = tid >> 3;
        const int s   = tid & 7;
        float* rp = sKq + row * S68 + s * 8;
        float4 v0 = *(float4*)rp;
        float4 v1 = *(float4*)(rp + 4);
        float m = fmaxf(fmaxf(fmaxf(v0.x, v0.y), fmaxf(v0.z, v0.w)),
                        fmaxf(fmaxf(v1.x, v1.y), fmaxf(v1.z, v1.w)));
        m = fmaxf(m, __shfl_xor_sync(0xffffffffu, m, 1));
        m = fmaxf(m, __shfl_xor_sync(0xffffffffu, m, 2));
        m = fmaxf(m, __shfl_xor_sync(0xffffffffu, m, 4));
        v0.x = __expf(v0.x - m); v0.y = __expf(v0.y - m);
        v0.z = __expf(v0.z - m); v0.w = __expf(v0.w - m);
        v1.x = __expf(v1.x - m); v1.y = __expf(v1.y - m);
        v1.z = __expf(v1.z - m); v1.w = __expf(v1.w - m);
        float su = v0.x + v0.y + v0.z + v0.w + v1.x + v1.y + v1.z + v1.w;
        su += __shfl_xor_sync(0xffffffffu, su, 1);
        su += __shfl_xor_sync(0xffffffffu, su, 2);
        su += __shfl_xor_sync(0xffffffffu, su, 4);
        float inv = 1.f / su;
        v0.x *= inv; v0.y *= inv; v0.z *= inv; v0.w *= inv;
        v1.x *= inv; v1.y *= inv; v1.z *= inv; v1.w *= inv;
        *(float4*)rp = v0;
        *(float4*)(rp + 4) = v1;
    }
    __syncthreads();

    // S3: Kqv = Kq @ V (32x64, contract 64)
    {
        const int tr = tid >> 4;
        const int tc = tid & 15;
        float4 acc0 = make_float4(0, 0, 0, 0);
        float4 acc1 = make_float4(0, 0, 0, 0);
        const float* r0 = sKq + (2 * tr) * S68;
        const float* r1 = r0 + S68;
        #pragma unroll
        for (int j4 = 0; j4 < 16; ++j4) {
            float4 a0 = *(const float4*)(r0 + j4 * 4);
            float4 a1 = *(const float4*)(r1 + j4 * 4);
            const float* vb = sV + (j4 * 4) * S68 + 4 * tc;
            float4 b0 = *(const float4*)(vb);
            float4 b1 = *(const float4*)(vb + S68);
            float4 b2 = *(const float4*)(vb + 2 * S68);
            float4 b3 = *(const float4*)(vb + 3 * S68);
            acc0.x += a0.x * b0.x + a0.y * b1.x + a0.z * b2.x + a0.w * b3.x;
            acc0.y += a0.x * b0.y + a0.y * b1.y + a0.z * b2.y + a0.w * b3.y;
            acc0.z += a0.x * b0.z + a0.y * b1.z + a0.z * b2.z + a0.w * b3.z;
            acc0.w += a0.x * b0.w + a0.y * b1.w + a0.z * b2.w + a0.w * b3.w;
            acc1.x += a1.x * b0.x + a1.y * b1.x + a1.z * b2.x + a1.w * b3.x;
            acc1.y += a1.x * b0.y + a1.y * b1.y + a1.z * b2.y + a1.w * b3.y;
            acc1.z += a1.x * b0.z + a1.y * b1.z + a1.z * b2.z + a1.w * b3.z;
            acc1.w += a1.x * b0.w + a1.y * b1.w + a1.z * b2.w + a1.w * b3.w;
        }
        *(float4*)(sKqv + (2 * tr) * S68 + 4 * tc) = acc0;
        *(float4*)(sKqv + (2 * tr + 1) * S68 + 4 * tc) = acc1;
    }
    __syncthreads();

    // S4: out = Qk @ Kqv (64x64, contract 32)
    {
        const int tr = tid >> 4;
        const int tc = tid & 15;
        float4 acc[4];
        #pragma unroll
        for (int i = 0; i < 4; ++i) acc[i] = make_float4(0, 0, 0, 0);
        #pragma unroll
        for (int j4 = 0; j4 < 8; ++j4) {
            float4 a[4];
            #pragma unroll
            for (int ii = 0; ii < 4; ++ii)
                a[ii] = *(const float4*)(sQk + (4 * tr + ii) * S36 + j4 * 4);
            const float* kb = sKqv + (j4 * 4) * S68 + 4 * tc;
            float4 b0 = *(const float4*)(kb);
            float4 b1 = *(const float4*)(kb + S68);
            float4 b2 = *(const float4*)(kb + 2 * S68);
            float4 b3 = *(const float4*)(kb + 3 * S68);
            #pragma unroll
            for (int ii = 0; ii < 4; ++ii) {
                acc[ii].x += a[ii].x * b0.x + a[ii].y * b1.x + a[ii].z * b2.x + a[ii].w * b3.x;
                acc[ii].y += a[ii].x * b0.y + a[ii].y * b1.y + a[ii].z * b2.y + a[ii].w * b3.y;
                acc[ii].z += a[ii].x * b0.z + a[ii].y * b1.z + a[ii].z * b2.z + a[ii].w * b3.z;
                acc[ii].w += a[ii].x * b0.w + a[ii].y * b1.w + a[ii].z * b2.w + a[ii].w * b3.w;
            }
        }
        #pragma unroll
        for (int ii = 0; ii < 4; ++ii)
            *(float4*)(gO + base + (4 * tr + ii) * 64 + 4 * tc) = acc[ii];
    }
}

// ---------------------------------------------------------------------------
// Transpose [B][C][N] -> [B][N][C]
// ---------------------------------------------------------------------------
__global__ __launch_bounds__(256) void transpose_kernel(
    const float* __restrict__ gO, float* __restrict__ out)
{
    __shared__ float tile[32][33];
    const int b  = blockIdx.z;
    const int n0 = blockIdx.x * 32;
    const int c0 = blockIdx.y * 32;
    const float* src = gO + ((size_t)b * 512) * 4096;
    #pragma unroll
    for (int i = threadIdx.y; i < 32; i += 8)
        tile[i][threadIdx.x] = src[(size_t)(c0 + i) * 4096 + n0 + threadIdx.x];
    __syncthreads();
    float* dst = out + ((size_t)b * 4096) * 512;
    #pragma unroll
    for (int i = threadIdx.y; i < 32; i += 8)
        dst[(size_t)(n0 + i) * 512 + c0 + threadIdx.x] = tile[threadIdx.x][i];
}

// ---------------------------------------------------------------------------
// Host side
// ---------------------------------------------------------------------------
extern "C" void kernel_launch(void* const* d_in, const int* in_sizes, int n_in,
                              void* d_out, int out_size)
{
    (void)in_sizes; (void)n_in; (void)out_size;
    const float* x  = (const float*)d_in[0];
    const float* Wq = (const float*)d_in[1];
    const float* bq = (const float*)d_in[2];
    const float* Wk = (const float*)d_in[3];
    const float* bk = (const float*)d_in[4];
    const float* Wv = (const float*)d_in[5];
    const float* bv = (const float*)d_in[6];
    float* out = (float*)d_out;

    float *pQ, *pK, *pV, *pO;
    cudaGetSymbolAddress((void**)&pQ, g_Q);
    cudaGetSymbolAddress((void**)&pK, g_K);
    cudaGetSymbolAddress((void**)&pV, g_V);
    cudaGetSymbolAddress((void**)&pO, g_O);

    __half *pxh, *pwh;
    cudaGetSymbolAddress((void**)&pxh, g_xh);
    cudaGetSymbolAddress((void**)&pwh, g_wh);

    convX_kernel<<<(MTOT * CDIM / 4 + 255) / 256, 256>>>(
        (const float4*)x, (__half2*)pxh, MTOT * CDIM / 4);
    convW_kernel<<<dim3((CDIM * CDIM / 4 + 255) / 256, 3), 256>>>(
        (const float4*)Wq, (const float4*)Wk, (const float4*)Wv, (__half2*)pwh);

    cudaFuncSetAttribute(proj_mma_kernel, cudaFuncAttributeMaxDynamicSharedMemorySize,
                         PROJ_SMEM);
    proj_mma_kernel<<<dim3(MTOT / 128, CDIM / 128, 3), 256, PROJ_SMEM>>>(
        pxh, pwh, bq, bk, bv);

    cudaFuncSetAttribute(attn_kernel, cudaFuncAttributeMaxDynamicSharedMemorySize,
                         ATT_SMEM_BYTES);
    attn_kernel<<<BATCH * CDIM, 256, ATT_SMEM_BYTES>>>(pQ, pK, pV, pO);

    transpose_kernel<<<dim3(NSEQ / 32, CDIM / 32, BATCH), dim3(32, 8)>>>(pO, out);
}

// round 7
// speedup vs baseline: 4.5864x; 1.3134x over previous
#include <cuda_runtime.h>
#include <cuda_fp16.h>
#include <math.h>
#include <stdint.h>

// ---------------------------------------------------------------------------
// Problem constants
// ---------------------------------------------------------------------------
#define BATCH 16
#define NSEQ 4096
#define CDIM 512
#define MTOT (BATCH * NSEQ)                       // 65536
#define ELEMS ((size_t)BATCH * CDIM * NSEQ)       // 33554432

__device__ float g_Q[ELEMS];
__device__ float g_K[ELEMS];
__device__ float g_V[ELEMS];
__device__ float g_O[ELEMS];

__device__ __half g_xh[(size_t)MTOT * CDIM];      // fp16 x
__device__ __half g_wh[3 * CDIM * CDIM];          // fp16 W (q,k,v)

__device__ __forceinline__ uint32_t smem_u32(const void* p) {
    uint32_t a;
    asm("{ .reg .u64 t; cvta.to.shared.u64 t, %1; cvt.u32.u64 %0, t; }"
        : "=r"(a) : "l"(p));
    return a;
}

// ---------------------------------------------------------------------------
// MMA / ldmatrix / cp.async macros
// ---------------------------------------------------------------------------
#define LDSM_X4(r0, r1, r2, r3, addr) \
    asm volatile("ldmatrix.sync.aligned.m8n8.x4.shared.b16 {%0,%1,%2,%3}, [%4];" \
        : "=r"(r0), "=r"(r1), "=r"(r2), "=r"(r3) : "r"(addr))

#define LDSM_X4T(r0, r1, r2, r3, addr) \
    asm volatile("ldmatrix.sync.aligned.m8n8.x4.trans.shared.b16 {%0,%1,%2,%3}, [%4];" \
        : "=r"(r0), "=r"(r1), "=r"(r2), "=r"(r3) : "r"(addr))

#define MMA_F16(c, a0, a1, a2, a3, b0, b1) \
    asm volatile("mma.sync.aligned.m16n8k16.row.col.f32.f16.f16.f32 " \
        "{%0,%1,%2,%3}, {%4,%5,%6,%7}, {%8,%9}, {%0,%1,%2,%3};" \
        : "+f"((c)[0]), "+f"((c)[1]), "+f"((c)[2]), "+f"((c)[3]) \
        : "r"(a0), "r"(a1), "r"(a2), "r"(a3), "r"(b0), "r"(b1))

#define CP_ASYNC16(dst, src) \
    asm volatile("cp.async.cg.shared.global [%0], [%1], 16;" \
        :: "r"(dst), "l"(src) : "memory")

// ---------------------------------------------------------------------------
// fp32 -> fp16 conversion kernels
// ---------------------------------------------------------------------------
__global__ __launch_bounds__(256) void convX_kernel(
    const float4* __restrict__ in, __half2* __restrict__ outp, int n4)
{
    int i = blockIdx.x * 256 + threadIdx.x;
    if (i >= n4) return;
    float4 v = in[i];
    outp[2 * i]     = __floats2half2_rn(v.x, v.y);
    outp[2 * i + 1] = __floats2half2_rn(v.z, v.w);
}

__global__ __launch_bounds__(256) void convW_kernel(
    const float4* __restrict__ Wq,
    const float4* __restrict__ Wk,
    const float4* __restrict__ Wv,
    __half2* __restrict__ outp)
{
    const int z = blockIdx.y;
    const float4* src = (z == 0) ? Wq : (z == 1) ? Wk : Wv;
    const int n4 = CDIM * CDIM / 4;
    int i = blockIdx.x * 256 + threadIdx.x;
    if (i >= n4) return;
    float4 v = src[i];
    __half2* o = outp + (size_t)z * n4 * 2;
    o[2 * i]     = __floats2half2_rn(v.x, v.y);
    o[2 * i + 1] = __floats2half2_rn(v.z, v.w);
}

// ---------------------------------------------------------------------------
// Projection GEMM via mma.sync (fp16, fp32 accum). Unchanged from round 6.
// ---------------------------------------------------------------------------
#define PTS 40
#define PTILE_B (128 * PTS * 2)
#define PSTAGE_B (2 * PTILE_B)
#define PROJ_SMEM (4 * PSTAGE_B)

__global__ __launch_bounds__(256, 2) void proj_mma_kernel(
    const __half* __restrict__ xh,
    const __half* __restrict__ whp,
    const float* __restrict__ biasq,
    const float* __restrict__ biask,
    const float* __restrict__ biasv)
{
    extern __shared__ __half smem[];
    const uint32_t smb = smem_u32(smem);

    const int tid  = threadIdx.x;
    const int lane = tid & 31;
    const int warp = tid >> 5;
    const int wm   = warp >> 2;
    const int wn   = warp & 3;

    const int z  = blockIdx.z;
    const int d0 = blockIdx.y * 128;
    const int n0 = blockIdx.x * 128;

    const __half* W = whp + (size_t)z * CDIM * CDIM;

    float acc[4][4][4];
    #pragma unroll
    for (int i = 0; i < 4; ++i)
        #pragma unroll
        for (int j = 0; j < 4; ++j)
            #pragma unroll
            for (int q = 0; q < 4; ++q) acc[i][j][q] = 0.f;

    const int lr = tid >> 1;
    const int lc = (tid & 1) * 16;

    #define LOAD_STAGE(s, k0) do { \
        const uint32_t db = smb + (s) * PSTAGE_B + (uint32_t)(lr * PTS + lc) * 2; \
        const size_t go = (size_t)lr * 512 + (k0) + lc; \
        CP_ASYNC16(db,                W + (size_t)d0 * 512 + go); \
        CP_ASYNC16(db + 16,           W + (size_t)d0 * 512 + go + 8); \
        CP_ASYNC16(db + PTILE_B,      xh + (size_t)n0 * 512 + go); \
        CP_ASYNC16(db + PTILE_B + 16, xh + (size_t)n0 * 512 + go + 8); \
    } while (0)

    LOAD_STAGE(0, 0);
    asm volatile("cp.async.commit_group;" ::: "memory");
    LOAD_STAGE(1, 32);
    asm volatile("cp.async.commit_group;" ::: "memory");
    LOAD_STAGE(2, 64);
    asm volatile("cp.async.commit_group;" ::: "memory");

    const int aRow  = wm * 64 + (lane & 15);
    const int aCol  = (lane >> 4) * 8;
    const int g     = lane >> 3;
    const int bRow  = wn * 32 + (g & 2) * 4 + (lane & 7);
    const int bElem = (g & 1) * 8;

    for (int kt = 0; kt < 16; ++kt) {
        asm volatile("cp.async.wait_group 2;" ::: "memory");
        __syncthreads();

        if (kt < 13) LOAD_STAGE((kt + 3) & 3, (kt + 3) * 32);
        asm volatile("cp.async.commit_group;" ::: "memory");

        const uint32_t sA = smb + (kt & 3) * PSTAGE_B;
        const uint32_t sB = sA + PTILE_B;

        #pragma unroll
        for (int kk = 0; kk < 2; ++kk) {
            uint32_t bh[4][2];
            #pragma unroll
            for (int p = 0; p < 2; ++p) {
                uint32_t ba = sB + (uint32_t)((bRow + p * 16) * PTS + kk * 16 + bElem) * 2;
                LDSM_X4(bh[2 * p][0], bh[2 * p][1], bh[2 * p + 1][0], bh[2 * p + 1][1], ba);
            }
            #pragma unroll
            for (int mi = 0; mi < 4; ++mi) {
                uint32_t aa = sA + (uint32_t)((aRow + mi * 16) * PTS + kk * 16 + aCol) * 2;
                uint32_t a0, a1, a2, a3;
                LDSM_X4(a0, a1, a2, a3, aa);
                #pragma unroll
                for (int ni = 0; ni < 4; ++ni)
                    MMA_F16(acc[mi][ni], a0, a1, a2, a3, bh[ni][0], bh[ni][1]);
            }
        }
    }

    const float* bias = (z == 0) ? biasq : (z == 1) ? biask : biasv;
    float* outp = (z == 0) ? g_Q : (z == 1) ? g_K : g_V;
    const int b  = n0 >> 12;
    const int nb = (n0 & 4095) + wn * 32 + (lane & 3) * 2;

    #pragma unroll
    for (int mi = 0; mi < 4; ++mi) {
        const int dA = d0 + wm * 64 + mi * 16 + (lane >> 2);
        const float bA = bias[dA];
        const float bB = bias[dA + 8];
        float* rowA = outp + (((size_t)(b * 512 + dA)) << 12) + nb;
        float* rowB = rowA + ((size_t)8 << 12);
        #pragma unroll
        for (int ni = 0; ni < 4; ++ni) {
            float2 vA, vB;
            vA.x = 1.f / (1.f + __expf(-(acc[mi][ni][0] + bA)));
            vA.y = 1.f / (1.f + __expf(-(acc[mi][ni][1] + bA)));
            vB.x = 1.f / (1.f + __expf(-(acc[mi][ni][2] + bB)));
            vB.y = 1.f / (1.f + __expf(-(acc[mi][ni][3] + bB)));
            *(float2*)(rowA + ni * 8) = vA;
            *(float2*)(rowB + ni * 8) = vB;
        }
    }
}

// ---------------------------------------------------------------------------
// Attention via fp16 tensor cores. One block per (b,c), 256 threads (8 warps).
// Q/K/V converted to fp16 smem; softmax in fp32 on GEMM outputs.
// ---------------------------------------------------------------------------
#define SH72 72        // half stride for 64-wide fp16 mats
#define SH40 40        // half stride for 32-wide fp16 mats
#define SF36 36        // float stride for 32-wide fp32 score mat
#define SF68 68        // float stride for 64-wide fp32 score mat

#define OFF_HQ   0
#define OFF_HK   9216
#define OFF_HV   18432
#define OFF_Hq   27648
#define OFF_Hk   32256
#define OFF_HQK  36864
#define OFF_HKQ  41984
#define OFF_HKQV 46592
#define OFF_S1   51200
#define OFF_S2   60416
#define ATT_SMEM_BYTES 69120

__global__ __launch_bounds__(256) void attn_kernel(
    const float* __restrict__ gQ,
    const float* __restrict__ gK,
    const float* __restrict__ gV,
    float* __restrict__ gO)
{
    extern __shared__ char sm8[];
    const uint32_t sb = smem_u32(sm8);
    __half* hQ   = (__half*)(sm8 + OFF_HQ);
    __half* hK   = (__half*)(sm8 + OFF_HK);
    __half* hV   = (__half*)(sm8 + OFF_HV);
    __half* hq   = (__half*)(sm8 + OFF_Hq);
    __half* hk   = (__half*)(sm8 + OFF_Hk);
    __half* hQk  = (__half*)(sm8 + OFF_HQK);
    __half* hKq  = (__half*)(sm8 + OFF_HKQ);
    __half* hKqv = (__half*)(sm8 + OFF_HKQV);
    float*  sS1  = (float*)(sm8 + OFF_S1);
    float*  sS2  = (float*)(sm8 + OFF_S2);

    const int bc = blockIdx.x;
    const size_t base = (size_t)bc * 4096;
    const int tid  = threadIdx.x;
    const int lane = tid & 31;
    const int warp = tid >> 5;

    // 1. load Q,K,V fp32 -> fp16 smem
    #pragma unroll
    for (int it = 0; it < 12; ++it) {
        int idx = tid + it * 256;              // 0..3071
        int m  = idx >> 10;                    // matrix select
        int r  = (idx >> 4) & 63;
        int c4 = (idx & 15) * 4;
        const float* src = (m == 0) ? gQ : (m == 1) ? gK : gV;
        float4 v = *(const float4*)(src + base + (r << 6) + c4);
        __half* dst = ((m == 0) ? hQ : (m == 1) ? hK : hV) + r * SH72 + c4;
        *(__half2*)(dst)     = __floats2half2_rn(v.x, v.y);
        *(__half2*)(dst + 2) = __floats2half2_rn(v.z, v.w);
    }
    __syncthreads();

    // 2. pool row pairs (fp16)
    {
        const __half2 hhalf = __float2half2_rn(0.5f);
        #pragma unroll
        for (int it = 0; it < 8; ++it) {
            int idx = tid + it * 256;          // 0..2047
            int which = idx >> 10;             // 0: q, 1: k
            int i  = (idx >> 5) & 31;
            int cc = (idx & 31) * 2;
            const __half* s = which ? hK : hQ;
            __half* d      = which ? hk : hq;
            __half2 a = *(const __half2*)(s + (2 * i) * SH72 + cc);
            __half2 b = *(const __half2*)(s + (2 * i + 1) * SH72 + cc);
            *(__half2*)(d + i * SH72 + cc) = __hmul2(__hadd2(a, b), hhalf);
        }
    }
    __syncthreads();

    const float scale = 0.044194173824159216f;   // 1/sqrt(512)
    // fragment lane coords
    const int aRow = lane & 15;
    const int aCol = (lane >> 4) * 8;
    const int g    = lane >> 3;
    const int bR   = (g & 2) * 4 + (lane & 7);
    const int bE   = (g & 1) * 8;
    const int tR   = (g & 1) * 8 + (lane & 7);  // trans: stored-row within k16
    const int tC   = (g >> 1) * 8;              // trans: stored-col (n) offset
    const int cr   = lane >> 2;
    const int ccol = (lane & 3) * 2;

    // 3. S1: Qk = scale * Q(64x64) @ k^T -> (64x32). warps 4(M) x 2(N)
    {
        const int wm = warp >> 1, wn = warp & 1;
        float acc[2][4] = {{0,0,0,0},{0,0,0,0}};
        #pragma unroll
        for (int ks = 0; ks < 4; ++ks) {
            uint32_t a0,a1,a2,a3,b0,b1,b2,b3;
            LDSM_X4(a0,a1,a2,a3, sb + OFF_HQ + (uint32_t)((wm*16 + aRow)*SH72 + ks*16 + aCol)*2);
            LDSM_X4(b0,b1,b2,b3, sb + OFF_Hk + (uint32_t)((wn*16 + bR)*SH72 + ks*16 + bE)*2);
            MMA_F16(acc[0], a0,a1,a2,a3, b0,b1);
            MMA_F16(acc[1], a0,a1,a2,a3, b2,b3);
        }
        #pragma unroll
        for (int nt = 0; nt < 2; ++nt) {
            float* p0 = sS1 + (wm*16 + cr) * SF36 + wn*16 + nt*8 + ccol;
            float* p1 = p0 + 8 * SF36;
            *(float2*)p0 = make_float2(acc[nt][0]*scale, acc[nt][1]*scale);
            *(float2*)p1 = make_float2(acc[nt][2]*scale, acc[nt][3]*scale);
        }
    }

    // 4. S2: Kq = scale * q(32x64) @ K^T -> (32x64). warps 2(M) x 4(N)
    {
        const int wm = warp >> 2, wn = warp & 3;
        float acc[2][4] = {{0,0,0,0},{0,0,0,0}};
        #pragma unroll
        for (int ks = 0; ks < 4; ++ks) {
            uint32_t a0,a1,a2,a3,b0,b1,b2,b3;
            LDSM_X4(a0,a1,a2,a3, sb + OFF_Hq + (uint32_t)((wm*16 + aRow)*SH72 + ks*16 + aCol)*2);
            LDSM_X4(b0,b1,b2,b3, sb + OFF_HK + (uint32_t)((wn*16 + bR)*SH72 + ks*16 + bE)*2);
            MMA_F16(acc[0], a0,a1,a2,a3, b0,b1);
            MMA_F16(acc[1], a0,a1,a2,a3, b2,b3);
        }
        #pragma unroll
        for (int nt = 0; nt < 2; ++nt) {
            float* p0 = sS2 + (wm*16 + cr) * SF68 + wn*16 + nt*8 + ccol;
            float* p1 = p0 + 8 * SF68;
            *(float2*)p0 = make_float2(acc[nt][0]*scale, acc[nt][1]*scale);
            *(float2*)p1 = make_float2(acc[nt][2]*scale, acc[nt][3]*scale);
        }
    }
    __syncthreads();

    // 5. softmax S1 rows (64x32) -> hQk fp16 [64][SH40]
    {
        const int row = tid >> 2;
        const int s   = tid & 3;
        float* rp = sS1 + row * SF36 + s * 8;
        float4 v0 = *(float4*)rp;
        float4 v1 = *(float4*)(rp + 4);
        float m = fmaxf(fmaxf(fmaxf(v0.x, v0.y), fmaxf(v0.z, v0.w)),
                        fmaxf(fmaxf(v1.x, v1.y), fmaxf(v1.z, v1.w)));
        m = fmaxf(m, __shfl_xor_sync(0xffffffffu, m, 1));
        m = fmaxf(m, __shfl_xor_sync(0xffffffffu, m, 2));
        v0.x = __expf(v0.x - m); v0.y = __expf(v0.y - m);
        v0.z = __expf(v0.z - m); v0.w = __expf(v0.w - m);
        v1.x = __expf(v1.x - m); v1.y = __expf(v1.y - m);
        v1.z = __expf(v1.z - m); v1.w = __expf(v1.w - m);
        float su = v0.x + v0.y + v0.z + v0.w + v1.x + v1.y + v1.z + v1.w;
        su += __shfl_xor_sync(0xffffffffu, su, 1);
        su += __shfl_xor_sync(0xffffffffu, su, 2);
        float inv = 1.f / su;
        __half* wp = hQk + row * SH40 + s * 8;
        *(__half2*)(wp)     = __floats2half2_rn(v0.x * inv, v0.y * inv);
        *(__half2*)(wp + 2) = __floats2half2_rn(v0.z * inv, v0.w * inv);
        *(__half2*)(wp + 4) = __floats2half2_rn(v1.x * inv, v1.y * inv);
        *(__half2*)(wp + 6) = __floats2half2_rn(v1.z * inv, v1.w * inv);
    }

    // 6. softmax S2 rows (32x64) -> hKq fp16 [32][SH72]
    {
        const int row = tid >> 3;
        const int s   = tid & 7;
        float* rp = sS2 + row * SF68 + s * 8;
        float4 v0 = *(float4*)rp;
        float4 v1 = *(float4*)(rp + 4);
        float m = fmaxf(fmaxf(fmaxf(v0.x, v0.y), fmaxf(v0.z, v0.w)),
                        fmaxf(fmaxf(v1.x, v1.y), fmaxf(v1.z, v1.w)));
        m = fmaxf(m, __shfl_xor_sync(0xffffffffu, m, 1));
        m = fmaxf(m, __shfl_xor_sync(0xffffffffu, m, 2));
        m = fmaxf(m, __shfl_xor_sync(0xffffffffu, m, 4));
        v0.x = __expf(v0.x - m); v0.y = __expf(v0.y - m);
        v0.z = __expf(v0.z - m); v0.w = __expf(v0.w - m);
        v1.x = __expf(v1.x - m); v1.y = __expf(v1.y - m);
        v1.z = __expf(v1.z - m); v1.w = __expf(v1.w - m);
        float su = v0.x + v0.y + v0.z + v0.w + v1.x + v1.y + v1.z + v1.w;
        su += __shfl_xor_sync(0xffffffffu, su, 1);
        su += __shfl_xor_sync(0xffffffffu, su, 2);
        su += __shfl_xor_sync(0xffffffffu, su, 4);
        float inv = 1.f / su;
        __half* wp = hKq + row * SH72 + s * 8;
        *(__half2*)(wp)     = __floats2half2_rn(v0.x * inv, v0.y * inv);
        *(__half2*)(wp + 2) = __floats2half2_rn(v0.z * inv, v0.w * inv);
        *(__half2*)(wp + 4) = __floats2half2_rn(v1.x * inv, v1.y * inv);
        *(__half2*)(wp + 6) = __floats2half2_rn(v1.z * inv, v1.w * inv);
    }
    __syncthreads();

    // 7. S3: Kqv = Kq(32x64) @ V(64x64) -> (32x64). warps 2(M) x 4(N). B=V trans.
    {
        const int wm = warp >> 2, wn = warp & 3;
        float acc[2][4] = {{0,0,0,0},{0,0,0,0}};
        #pragma unroll
        for (int ks = 0; ks < 4; ++ks) {
            uint32_t a0,a1,a2,a3,b0,b1,b2,b3;
            LDSM_X4(a0,a1,a2,a3, sb + OFF_HKQ + (uint32_t)((wm*16 + aRow)*SH72 + ks*16 + aCol)*2);
            LDSM_X4T(b0,b1,b2,b3, sb + OFF_HV + (uint32_t)((ks*16 + tR)*SH72 + wn*16 + tC)*2);
            MMA_F16(acc[0], a0,a1,a2,a3, b0,b1);
            MMA_F16(acc[1], a0,a1,a2,a3, b2,b3);
        }
        #pragma unroll
        for (int nt = 0; nt < 2; ++nt) {
            __half* p0 = hKqv + (wm*16 + cr) * SH72 + wn*16 + nt*8 + ccol;
            __half* p1 = p0 + 8 * SH72;
            *(__half2*)p0 = __floats2half2_rn(acc[nt][0], acc[nt][1]);
            *(__half2*)p1 = __floats2half2_rn(acc[nt][2], acc[nt][3]);
        }
    }
    __syncthreads();

    // 8. S4: out = Qk(64x32) @ Kqv(32x64) -> (64x64). warps 4(M) x 2(N), n32/warp.
    {
        const int wm = warp >> 1, wn = warp & 1;
        float acc[4][4];
        #pragma unroll
        for (int i = 0; i < 4; ++i)
            #pragma unroll
            for (int q = 0; q < 4; ++q) acc[i][q] = 0.f;
        #pragma unroll
        for (int ks = 0; ks < 2; ++ks) {
            uint32_t a0,a1,a2,a3;
            LDSM_X4(a0,a1,a2,a3, sb + OFF_HQK + (uint32_t)((wm*16 + aRow)*SH40 + ks*16 + aCol)*2);
            #pragma unroll
            for (int nh = 0; nh < 2; ++nh) {
                uint32_t b0,b1,b2,b3;
                LDSM_X4T(b0,b1,b2,b3,
                    sb + OFF_HKQV + (uint32_t)((ks*16 + tR)*SH72 + wn*32 + nh*16 + tC)*2);
                MMA_F16(acc[nh*2+0], a0,a1,a2,a3, b0,b1);
                MMA_F16(acc[nh*2+1], a0,a1,a2,a3, b2,b3);
            }
        }
        #pragma unroll
        for (int nt = 0; nt < 4; ++nt) {
            float* p0 = gO + base + (wm*16 + cr) * 64 + wn*32 + nt*8 + ccol;
            float* p1 = p0 + 8 * 64;
            *(float2*)p0 = make_float2(acc[nt][0], acc[nt][1]);
            *(float2*)p1 = make_float2(acc[nt][2], acc[nt][3]);
        }
    }
}

// ---------------------------------------------------------------------------
// Transpose [B][C][N] -> [B][N][C]
// ---------------------------------------------------------------------------
__global__ __launch_bounds__(256) void transpose_kernel(
    const float* __restrict__ gO, float* __restrict__ out)
{
    __shared__ float tile[32][33];
    const int b  = blockIdx.z;
    const int n0 = blockIdx.x * 32;
    const int c0 = blockIdx.y * 32;
    const float* src = gO + ((size_t)b * 512) * 4096;
    #pragma unroll
    for (int i = threadIdx.y; i < 32; i += 8)
        tile[i][threadIdx.x] = src[(size_t)(c0 + i) * 4096 + n0 + threadIdx.x];
    __syncthreads();
    float* dst = out + ((size_t)b * 4096) * 512;
    #pragma unroll
    for (int i = threadIdx.y; i < 32; i += 8)
        dst[(size_t)(n0 + i) * 512 + c0 + threadIdx.x] = tile[threadIdx.x][i];
}

// ---------------------------------------------------------------------------
// Host side
// ---------------------------------------------------------------------------
extern "C" void kernel_launch(void* const* d_in, const int* in_sizes, int n_in,
                              void* d_out, int out_size)
{
    (void)in_sizes; (void)n_in; (void)out_size;
    const float* x  = (const float*)d_in[0];
    const float* Wq = (const float*)d_in[1];
    const float* bq = (const float*)d_in[2];
    const float* Wk = (const float*)d_in[3];
    const float* bk = (const float*)d_in[4];
    const float* Wv = (const float*)d_in[5];
    const float* bv = (const float*)d_in[6];
    float* out = (float*)d_out;

    float *pQ, *pK, *pV, *pO;
    cudaGetSymbolAddress((void**)&pQ, g_Q);
    cudaGetSymbolAddress((void**)&pK, g_K);
    cudaGetSymbolAddress((void**)&pV, g_V);
    cudaGetSymbolAddress((void**)&pO, g_O);

    __half *pxh, *pwh;
    cudaGetSymbolAddress((void**)&pxh, g_xh);
    cudaGetSymbolAddress((void**)&pwh, g_wh);

    convX_kernel<<<(MTOT * CDIM / 4 + 255) / 256, 256>>>(
        (const float4*)x, (__half2*)pxh, MTOT * CDIM / 4);
    convW_kernel<<<dim3((CDIM * CDIM / 4 + 255) / 256, 3), 256>>>(
        (const float4*)Wq, (const float4*)Wk, (const float4*)Wv, (__half2*)pwh);

    cudaFuncSetAttribute(proj_mma_kernel, cudaFuncAttributeMaxDynamicSharedMemorySize,
                         PROJ_SMEM);
    proj_mma_kernel<<<dim3(MTOT / 128, CDIM / 128, 3), 256, PROJ_SMEM>>>(
        pxh, pwh, bq, bk, bv);

    cudaFuncSetAttribute(attn_kernel, cudaFuncAttributeMaxDynamicSharedMemorySize,
                         ATT_SMEM_BYTES);
    attn_kernel<<<BATCH * CDIM, 256, ATT_SMEM_BYTES>>>(pQ, pK, pV, pO);

    transpose_kernel<<<dim3(NSEQ / 32, CDIM / 32, BATCH), dim3(32, 8)>>>(pO, out);
}

// round 8
// speedup vs baseline: 4.8064x; 1.0480x over previous
#include <cuda_runtime.h>
#include <cuda_fp16.h>
#include <math.h>
#include <stdint.h>

// ---------------------------------------------------------------------------
// Problem constants
// ---------------------------------------------------------------------------
#define BATCH 16
#define NSEQ 4096
#define CDIM 512
#define MTOT (BATCH * NSEQ)                       // 65536
#define ELEMS ((size_t)BATCH * CDIM * NSEQ)       // 33554432

__device__ __half g_Qh[ELEMS];     // fp16 Q,K,V scratch (channel-major)
__device__ __half g_Kh[ELEMS];
__device__ __half g_Vh[ELEMS];
__device__ __half g_Oh[ELEMS];     // fp16 attention output (channel-major)

__device__ __half g_xh[(size_t)MTOT * CDIM];      // fp16 x
__device__ __half g_wh[3 * CDIM * CDIM];          // fp16 W (q,k,v)

__device__ __forceinline__ uint32_t smem_u32(const void* p) {
    uint32_t a;
    asm("{ .reg .u64 t; cvta.to.shared.u64 t, %1; cvt.u32.u64 %0, t; }"
        : "=r"(a) : "l"(p));
    return a;
}

// ---------------------------------------------------------------------------
// MMA / ldmatrix / cp.async macros
// ---------------------------------------------------------------------------
#define LDSM_X4(r0, r1, r2, r3, addr) \
    asm volatile("ldmatrix.sync.aligned.m8n8.x4.shared.b16 {%0,%1,%2,%3}, [%4];" \
        : "=r"(r0), "=r"(r1), "=r"(r2), "=r"(r3) : "r"(addr))

#define LDSM_X4T(r0, r1, r2, r3, addr) \
    asm volatile("ldmatrix.sync.aligned.m8n8.x4.trans.shared.b16 {%0,%1,%2,%3}, [%4];" \
        : "=r"(r0), "=r"(r1), "=r"(r2), "=r"(r3) : "r"(addr))

#define MMA_F16(c, a0, a1, a2, a3, b0, b1) \
    asm volatile("mma.sync.aligned.m16n8k16.row.col.f32.f16.f16.f32 " \
        "{%0,%1,%2,%3}, {%4,%5,%6,%7}, {%8,%9}, {%0,%1,%2,%3};" \
        : "+f"((c)[0]), "+f"((c)[1]), "+f"((c)[2]), "+f"((c)[3]) \
        : "r"(a0), "r"(a1), "r"(a2), "r"(a3), "r"(b0), "r"(b1))

#define CP_ASYNC16(dst, src) \
    asm volatile("cp.async.cg.shared.global [%0], [%1], 16;" \
        :: "r"(dst), "l"(src) : "memory")

// ---------------------------------------------------------------------------
// fp32 -> fp16 conversion kernels
// ---------------------------------------------------------------------------
__global__ __launch_bounds__(256) void convX_kernel(
    const float4* __restrict__ in, __half2* __restrict__ outp, int n4)
{
    int i = blockIdx.x * 256 + threadIdx.x;
    if (i >= n4) return;
    float4 v = in[i];
    outp[2 * i]     = __floats2half2_rn(v.x, v.y);
    outp[2 * i + 1] = __floats2half2_rn(v.z, v.w);
}

__global__ __launch_bounds__(256) void convW_kernel(
    const float4* __restrict__ Wq,
    const float4* __restrict__ Wk,
    const float4* __restrict__ Wv,
    __half2* __restrict__ outp)
{
    const int z = blockIdx.y;
    const float4* src = (z == 0) ? Wq : (z == 1) ? Wk : Wv;
    const int n4 = CDIM * CDIM / 4;
    int i = blockIdx.x * 256 + threadIdx.x;
    if (i >= n4) return;
    float4 v = src[i];
    __half2* o = outp + (size_t)z * n4 * 2;
    o[2 * i]     = __floats2half2_rn(v.x, v.y);
    o[2 * i + 1] = __floats2half2_rn(v.z, v.w);
}

// ---------------------------------------------------------------------------
// Projection GEMM via mma.sync (fp16, fp32 accum). fp16 epilogue writes.
// ---------------------------------------------------------------------------
#define PTS 40
#define PTILE_B (128 * PTS * 2)
#define PSTAGE_B (2 * PTILE_B)
#define PROJ_SMEM (4 * PSTAGE_B)

__global__ __launch_bounds__(256, 2) void proj_mma_kernel(
    const __half* __restrict__ xh,
    const __half* __restrict__ whp,
    const float* __restrict__ biasq,
    const float* __restrict__ biask,
    const float* __restrict__ biasv)
{
    extern __shared__ __half smem[];
    const uint32_t smb = smem_u32(smem);

    const int tid  = threadIdx.x;
    const int lane = tid & 31;
    const int warp = tid >> 5;
    const int wm   = warp >> 2;
    const int wn   = warp & 3;

    const int z  = blockIdx.z;
    const int d0 = blockIdx.y * 128;
    const int n0 = blockIdx.x * 128;

    const __half* W = whp + (size_t)z * CDIM * CDIM;

    float acc[4][4][4];
    #pragma unroll
    for (int i = 0; i < 4; ++i)
        #pragma unroll
        for (int j = 0; j < 4; ++j)
            #pragma unroll
            for (int q = 0; q < 4; ++q) acc[i][j][q] = 0.f;

    const int lr = tid >> 1;
    const int lc = (tid & 1) * 16;

    #define LOAD_STAGE(s, k0) do { \
        const uint32_t db = smb + (s) * PSTAGE_B + (uint32_t)(lr * PTS + lc) * 2; \
        const size_t go = (size_t)lr * 512 + (k0) + lc; \
        CP_ASYNC16(db,                W + (size_t)d0 * 512 + go); \
        CP_ASYNC16(db + 16,           W + (size_t)d0 * 512 + go + 8); \
        CP_ASYNC16(db + PTILE_B,      xh + (size_t)n0 * 512 + go); \
        CP_ASYNC16(db + PTILE_B + 16, xh + (size_t)n0 * 512 + go + 8); \
    } while (0)

    LOAD_STAGE(0, 0);
    asm volatile("cp.async.commit_group;" ::: "memory");
    LOAD_STAGE(1, 32);
    asm volatile("cp.async.commit_group;" ::: "memory");
    LOAD_STAGE(2, 64);
    asm volatile("cp.async.commit_group;" ::: "memory");

    const int aRow  = wm * 64 + (lane & 15);
    const int aCol  = (lane >> 4) * 8;
    const int g     = lane >> 3;
    const int bRow  = wn * 32 + (g & 2) * 4 + (lane & 7);
    const int bElem = (g & 1) * 8;

    for (int kt = 0; kt < 16; ++kt) {
        asm volatile("cp.async.wait_group 2;" ::: "memory");
        __syncthreads();

        if (kt < 13) LOAD_STAGE((kt + 3) & 3, (kt + 3) * 32);
        asm volatile("cp.async.commit_group;" ::: "memory");

        const uint32_t sA = smb + (kt & 3) * PSTAGE_B;
        const uint32_t sB = sA + PTILE_B;

        #pragma unroll
        for (int kk = 0; kk < 2; ++kk) {
            uint32_t bh[4][2];
            #pragma unroll
            for (int p = 0; p < 2; ++p) {
                uint32_t ba = sB + (uint32_t)((bRow + p * 16) * PTS + kk * 16 + bElem) * 2;
                LDSM_X4(bh[2 * p][0], bh[2 * p][1], bh[2 * p + 1][0], bh[2 * p + 1][1], ba);
            }
            #pragma unroll
            for (int mi = 0; mi < 4; ++mi) {
                uint32_t aa = sA + (uint32_t)((aRow + mi * 16) * PTS + kk * 16 + aCol) * 2;
                uint32_t a0, a1, a2, a3;
                LDSM_X4(a0, a1, a2, a3, aa);
                #pragma unroll
                for (int ni = 0; ni < 4; ++ni)
                    MMA_F16(acc[mi][ni], a0, a1, a2, a3, bh[ni][0], bh[ni][1]);
            }
        }
    }

    const float* bias = (z == 0) ? biasq : (z == 1) ? biask : biasv;
    __half* outp = (z == 0) ? g_Qh : (z == 1) ? g_Kh : g_Vh;
    const int b  = n0 >> 12;
    const int nb = (n0 & 4095) + wn * 32 + (lane & 3) * 2;

    #pragma unroll
    for (int mi = 0; mi < 4; ++mi) {
        const int dA = d0 + wm * 64 + mi * 16 + (lane >> 2);
        const float bA = bias[dA];
        const float bB = bias[dA + 8];
        __half* rowA = outp + (((size_t)(b * 512 + dA)) << 12) + nb;
        __half* rowB = rowA + ((size_t)8 << 12);
        #pragma unroll
        for (int ni = 0; ni < 4; ++ni) {
            float s0 = 1.f / (1.f + __expf(-(acc[mi][ni][0] + bA)));
            float s1 = 1.f / (1.f + __expf(-(acc[mi][ni][1] + bA)));
            float s2 = 1.f / (1.f + __expf(-(acc[mi][ni][2] + bB)));
            float s3 = 1.f / (1.f + __expf(-(acc[mi][ni][3] + bB)));
            *(__half2*)(rowA + ni * 8) = __floats2half2_rn(s0, s1);
            *(__half2*)(rowB + ni * 8) = __floats2half2_rn(s2, s3);
        }
    }
}

// ---------------------------------------------------------------------------
// Attention via fp16 tensor cores. One block per (b,c), 256 threads (8 warps).
// fp16 in / fp16 out; softmax in fp32 on GEMM outputs.
// ---------------------------------------------------------------------------
#define SH72 72        // half stride for 64-wide fp16 mats
#define SH40 40        // half stride for 32-wide fp16 mats
#define SF36 36        // float stride for 32-wide fp32 score mat
#define SF68 68        // float stride for 64-wide fp32 score mat

#define OFF_HQ   0
#define OFF_HK   9216
#define OFF_HV   18432
#define OFF_Hq   27648
#define OFF_Hk   32256
#define OFF_HQK  36864
#define OFF_HKQ  41984
#define OFF_HKQV 46592
#define OFF_S1   51200
#define OFF_S2   60416
#define ATT_SMEM_BYTES 69120

__global__ __launch_bounds__(256) void attn_kernel(
    const __half* __restrict__ gQ,
    const __half* __restrict__ gK,
    const __half* __restrict__ gV,
    __half* __restrict__ gO)
{
    extern __shared__ char sm8[];
    const uint32_t sb = smem_u32(sm8);
    __half* hQ   = (__half*)(sm8 + OFF_HQ);
    __half* hK   = (__half*)(sm8 + OFF_HK);
    __half* hV   = (__half*)(sm8 + OFF_HV);
    __half* hq   = (__half*)(sm8 + OFF_Hq);
    __half* hk   = (__half*)(sm8 + OFF_Hk);
    __half* hQk  = (__half*)(sm8 + OFF_HQK);
    __half* hKq  = (__half*)(sm8 + OFF_HKQ);
    __half* hKqv = (__half*)(sm8 + OFF_HKQV);
    float*  sS1  = (float*)(sm8 + OFF_S1);
    float*  sS2  = (float*)(sm8 + OFF_S2);

    const int bc = blockIdx.x;
    const size_t base = (size_t)bc * 4096;
    const int tid  = threadIdx.x;
    const int lane = tid & 31;
    const int warp = tid >> 5;

    // 1. load Q,K,V fp16 -> smem (16B chunks, direct copy)
    #pragma unroll
    for (int it = 0; it < 6; ++it) {
        int idx = tid + it * 256;              // 0..1535
        int m    = idx >> 9;                   // matrix select (512 chunks each)
        int rest = idx & 511;
        int r    = rest >> 3;                  // row 0..63
        int c8   = (rest & 7) * 8;             // col offset (halfs)
        const __half* src = (m == 0) ? gQ : (m == 1) ? gK : gV;
        uint4 v = *(const uint4*)(src + base + (r << 6) + c8);
        __half* dst = ((m == 0) ? hQ : (m == 1) ? hK : hV) + r * SH72 + c8;
        *(uint4*)dst = v;
    }
    __syncthreads();

    // 2. pool row pairs (fp16)
    {
        const __half2 hhalf = __float2half2_rn(0.5f);
        #pragma unroll
        for (int it = 0; it < 8; ++it) {
            int idx = tid + it * 256;          // 0..2047
            int which = idx >> 10;             // 0: q, 1: k
            int i  = (idx >> 5) & 31;
            int cc = (idx & 31) * 2;
            const __half* s = which ? hK : hQ;
            __half* d      = which ? hk : hq;
            __half2 a = *(const __half2*)(s + (2 * i) * SH72 + cc);
            __half2 b = *(const __half2*)(s + (2 * i + 1) * SH72 + cc);
            *(__half2*)(d + i * SH72 + cc) = __hmul2(__hadd2(a, b), hhalf);
        }
    }
    __syncthreads();

    const float scale = 0.044194173824159216f;   // 1/sqrt(512)
    const int aRow = lane & 15;
    const int aCol = (lane >> 4) * 8;
    const int g    = lane >> 3;
    const int bR   = (g & 2) * 4 + (lane & 7);
    const int bE   = (g & 1) * 8;
    const int tR   = (g & 1) * 8 + (lane & 7);
    const int tC   = (g >> 1) * 8;
    const int cr   = lane >> 2;
    const int ccol = (lane & 3) * 2;

    // 3. S1: Qk = scale * Q(64x64) @ k^T -> (64x32). warps 4(M) x 2(N)
    {
        const int wm = warp >> 1, wn = warp & 1;
        float acc[2][4] = {{0,0,0,0},{0,0,0,0}};
        #pragma unroll
        for (int ks = 0; ks < 4; ++ks) {
            uint32_t a0,a1,a2,a3,b0,b1,b2,b3;
            LDSM_X4(a0,a1,a2,a3, sb + OFF_HQ + (uint32_t)((wm*16 + aRow)*SH72 + ks*16 + aCol)*2);
            LDSM_X4(b0,b1,b2,b3, sb + OFF_Hk + (uint32_t)((wn*16 + bR)*SH72 + ks*16 + bE)*2);
            MMA_F16(acc[0], a0,a1,a2,a3, b0,b1);
            MMA_F16(acc[1], a0,a1,a2,a3, b2,b3);
        }
        #pragma unroll
        for (int nt = 0; nt < 2; ++nt) {
            float* p0 = sS1 + (wm*16 + cr) * SF36 + wn*16 + nt*8 + ccol;
            float* p1 = p0 + 8 * SF36;
            *(float2*)p0 = make_float2(acc[nt][0]*scale, acc[nt][1]*scale);
            *(float2*)p1 = make_float2(acc[nt][2]*scale, acc[nt][3]*scale);
        }
    }

    // 4. S2: Kq = scale * q(32x64) @ K^T -> (32x64). warps 2(M) x 4(N)
    {
        const int wm = warp >> 2, wn = warp & 3;
        float acc[2][4] = {{0,0,0,0},{0,0,0,0}};
        #pragma unroll
        for (int ks = 0; ks < 4; ++ks) {
            uint32_t a0,a1,a2,a3,b0,b1,b2,b3;
            LDSM_X4(a0,a1,a2,a3, sb + OFF_Hq + (uint32_t)((wm*16 + aRow)*SH72 + ks*16 + aCol)*2);
            LDSM_X4(b0,b1,b2,b3, sb + OFF_HK + (uint32_t)((wn*16 + bR)*SH72 + ks*16 + bE)*2);
            MMA_F16(acc[0], a0,a1,a2,a3, b0,b1);
            MMA_F16(acc[1], a0,a1,a2,a3, b2,b3);
        }
        #pragma unroll
        for (int nt = 0; nt < 2; ++nt) {
            float* p0 = sS2 + (wm*16 + cr) * SF68 + wn*16 + nt*8 + ccol;
            float* p1 = p0 + 8 * SF68;
            *(float2*)p0 = make_float2(acc[nt][0]*scale, acc[nt][1]*scale);
            *(float2*)p1 = make_float2(acc[nt][2]*scale, acc[nt][3]*scale);
        }
    }
    __syncthreads();

    // 5. softmax S1 rows (64x32) -> hQk fp16 [64][SH40]
    {
        const int row = tid >> 2;
        const int s   = tid & 3;
        float* rp = sS1 + row * SF36 + s * 8;
        float4 v0 = *(float4*)rp;
        float4 v1 = *(float4*)(rp + 4);
        float m = fmaxf(fmaxf(fmaxf(v0.x, v0.y), fmaxf(v0.z, v0.w)),
                        fmaxf(fmaxf(v1.x, v1.y), fmaxf(v1.z, v1.w)));
        m = fmaxf(m, __shfl_xor_sync(0xffffffffu, m, 1));
        m = fmaxf(m, __shfl_xor_sync(0xffffffffu, m, 2));
        v0.x = __expf(v0.x - m); v0.y = __expf(v0.y - m);
        v0.z = __expf(v0.z - m); v0.w = __expf(v0.w - m);
        v1.x = __expf(v1.x - m); v1.y = __expf(v1.y - m);
        v1.z = __expf(v1.z - m); v1.w = __expf(v1.w - m);
        float su = v0.x + v0.y + v0.z + v0.w + v1.x + v1.y + v1.z + v1.w;
        su += __shfl_xor_sync(0xffffffffu, su, 1);
        su += __shfl_xor_sync(0xffffffffu, su, 2);
        float inv = 1.f / su;
        __half* wp = hQk + row * SH40 + s * 8;
        *(__half2*)(wp)     = __floats2half2_rn(v0.x * inv, v0.y * inv);
        *(__half2*)(wp + 2) = __floats2half2_rn(v0.z * inv, v0.w * inv);
        *(__half2*)(wp + 4) = __floats2half2_rn(v1.x * inv, v1.y * inv);
        *(__half2*)(wp + 6) = __floats2half2_rn(v1.z * inv, v1.w * inv);
    }

    // 6. softmax S2 rows (32x64) -> hKq fp16 [32][SH72]
    {
        const int row = tid >> 3;
        const int s   = tid & 7;
        float* rp = sS2 + row * SF68 + s * 8;
        float4 v0 = *(float4*)rp;
        float4 v1 = *(float4*)(rp + 4);
        float m = fmaxf(fmaxf(fmaxf(v0.x, v0.y), fmaxf(v0.z, v0.w)),
                        fmaxf(fmaxf(v1.x, v1.y), fmaxf(v1.z, v1.w)));
        m = fmaxf(m, __shfl_xor_sync(0xffffffffu, m, 1));
        m = fmaxf(m, __shfl_xor_sync(0xffffffffu, m, 2));
        m = fmaxf(m, __shfl_xor_sync(0xffffffffu, m, 4));
        v0.x = __expf(v0.x - m); v0.y = __expf(v0.y - m);
        v0.z = __expf(v0.z - m); v0.w = __expf(v0.w - m);
        v1.x = __expf(v1.x - m); v1.y = __expf(v1.y - m);
        v1.z = __expf(v1.z - m); v1.w = __expf(v1.w - m);
        float su = v0.x + v0.y + v0.z + v0.w + v1.x + v1.y + v1.z + v1.w;
        su += __shfl_xor_sync(0xffffffffu, su, 1);
        su += __shfl_xor_sync(0xffffffffu, su, 2);
        su += __shfl_xor_sync(0xffffffffu, su, 4);
        float inv = 1.f / su;
        __half* wp = hKq + row * SH72 + s * 8;
        *(__half2*)(wp)     = __floats2half2_rn(v0.x * inv, v0.y * inv);
        *(__half2*)(wp + 2) = __floats2half2_rn(v0.z * inv, v0.w * inv);
        *(__half2*)(wp + 4) = __floats2half2_rn(v1.x * inv, v1.y * inv);
        *(__half2*)(wp + 6) = __floats2half2_rn(v1.z * inv, v1.w * inv);
    }
    __syncthreads();

    // 7. S3: Kqv = Kq(32x64) @ V(64x64) -> (32x64). warps 2(M) x 4(N). B=V trans.
    {
        const int wm = warp >> 2, wn = warp & 3;
        float acc[2][4] = {{0,0,0,0},{0,0,0,0}};
        #pragma unroll
        for (int ks = 0; ks < 4; ++ks) {
            uint32_t a0,a1,a2,a3,b0,b1,b2,b3;
            LDSM_X4(a0,a1,a2,a3, sb + OFF_HKQ + (uint32_t)((wm*16 + aRow)*SH72 + ks*16 + aCol)*2);
            LDSM_X4T(b0,b1,b2,b3, sb + OFF_HV + (uint32_t)((ks*16 + tR)*SH72 + wn*16 + tC)*2);
            MMA_F16(acc[0], a0,a1,a2,a3, b0,b1);
            MMA_F16(acc[1], a0,a1,a2,a3, b2,b3);
        }
        #pragma unroll
        for (int nt = 0; nt < 2; ++nt) {
            __half* p0 = hKqv + (wm*16 + cr) * SH72 + wn*16 + nt*8 + ccol;
            __half* p1 = p0 + 8 * SH72;
            *(__half2*)p0 = __floats2half2_rn(acc[nt][0], acc[nt][1]);
            *(__half2*)p1 = __floats2half2_rn(acc[nt][2], acc[nt][3]);
        }
    }
    __syncthreads();

    // 8. S4: out = Qk(64x32) @ Kqv(32x64) -> (64x64). warps 4(M) x 2(N).
    {
        const int wm = warp >> 1, wn = warp & 1;
        float acc[4][4];
        #pragma unroll
        for (int i = 0; i < 4; ++i)
            #pragma unroll
            for (int q = 0; q < 4; ++q) acc[i][q] = 0.f;
        #pragma unroll
        for (int ks = 0; ks < 2; ++ks) {
            uint32_t a0,a1,a2,a3;
            LDSM_X4(a0,a1,a2,a3, sb + OFF_HQK + (uint32_t)((wm*16 + aRow)*SH40 + ks*16 + aCol)*2);
            #pragma unroll
            for (int nh = 0; nh < 2; ++nh) {
                uint32_t b0,b1,b2,b3;
                LDSM_X4T(b0,b1,b2,b3,
                    sb + OFF_HKQV + (uint32_t)((ks*16 + tR)*SH72 + wn*32 + nh*16 + tC)*2);
                MMA_F16(acc[nh*2+0], a0,a1,a2,a3, b0,b1);
                MMA_F16(acc[nh*2+1], a0,a1,a2,a3, b2,b3);
            }
        }
        #pragma unroll
        for (int nt = 0; nt < 4; ++nt) {
            __half* p0 = gO + base + (wm*16 + cr) * 64 + wn*32 + nt*8 + ccol;
            __half* p1 = p0 + 8 * 64;
            *(__half2*)p0 = __floats2half2_rn(acc[nt][0], acc[nt][1]);
            *(__half2*)p1 = __floats2half2_rn(acc[nt][2], acc[nt][3]);
        }
    }
}

// ---------------------------------------------------------------------------
// Transpose [B][C][N] fp16 -> [B][N][C] fp32
// ---------------------------------------------------------------------------
__global__ __launch_bounds__(256) void transpose_kernel(
    const __half* __restrict__ gO, float* __restrict__ out)
{
    __shared__ float tile[32][33];
    const int b  = blockIdx.z;
    const int n0 = blockIdx.x * 32;
    const int c0 = blockIdx.y * 32;
    const __half* src = gO + ((size_t)b * 512) * 4096;
    #pragma unroll
    for (int i = threadIdx.y; i < 32; i += 8)
        tile[i][threadIdx.x] = __half2float(src[(size_t)(c0 + i) * 4096 + n0 + threadIdx.x]);
    __syncthreads();
    float* dst = out + ((size_t)b * 4096) * 512;
    #pragma unroll
    for (int i = threadIdx.y; i < 32; i += 8)
        dst[(size_t)(n0 + i) * 512 + c0 + threadIdx.x] = tile[threadIdx.x][i];
}

// ---------------------------------------------------------------------------
// Host side
// ---------------------------------------------------------------------------
extern "C" void kernel_launch(void* const* d_in, const int* in_sizes, int n_in,
                              void* d_out, int out_size)
{
    (void)in_sizes; (void)n_in; (void)out_size;
    const float* x  = (const float*)d_in[0];
    const float* Wq = (const float*)d_in[1];
    const float* bq = (const float*)d_in[2];
    const float* Wk = (const float*)d_in[3];
    const float* bk = (const float*)d_in[4];
    const float* Wv = (const float*)d_in[5];
    const float* bv = (const float*)d_in[6];
    float* out = (float*)d_out;

    __half *pQ, *pK, *pV, *pO, *pxh, *pwh;
    cudaGetSymbolAddress((void**)&pQ, g_Qh);
    cudaGetSymbolAddress((void**)&pK, g_Kh);
    cudaGetSymbolAddress((void**)&pV, g_Vh);
    cudaGetSymbolAddress((void**)&pO, g_Oh);
    cudaGetSymbolAddress((void**)&pxh, g_xh);
    cudaGetSymbolAddress((void**)&pwh, g_wh);

    convX_kernel<<<(MTOT * CDIM / 4 + 255) / 256, 256>>>(
        (const float4*)x, (__half2*)pxh, MTOT * CDIM / 4);
    convW_kernel<<<dim3((CDIM * CDIM / 4 + 255) / 256, 3), 256>>>(
        (const float4*)Wq, (const float4*)Wk, (const float4*)Wv, (__half2*)pwh);

    cudaFuncSetAttribute(proj_mma_kernel, cudaFuncAttributeMaxDynamicSharedMemorySize,
                         PROJ_SMEM);
    proj_mma_kernel<<<dim3(MTOT / 128, CDIM / 128, 3), 256, PROJ_SMEM>>>(
        pxh, pwh, bq, bk, bv);

    cudaFuncSetAttribute(attn_kernel, cudaFuncAttributeMaxDynamicSharedMemorySize,
                         ATT_SMEM_BYTES);
    attn_kernel<<<BATCH * CDIM, 256, ATT_SMEM_BYTES>>>(pQ, pK, pV, pO);

    transpose_kernel<<<dim3(NSEQ / 32, CDIM / 32, BATCH), dim3(32, 8)>>>(pO, out);
}